// round 14
// baseline (speedup 1.0000x reference)
#include <cuda_runtime.h>
#include <cuda_bf16.h>
#include <cstdint>

// ---------------- problem constants ----------------
#define VDIM 50000
#define VPAD 50048          // 782*64, padded for bf16 beta array
#define KDIM 50
#define HDIM 300
#define BDIM 512
#define NTOT 351            // 300 (W1 cols) + 51 (sbeta/bow_w cols)
#define BN_EPS 1e-5f
#define S2_KPAD 320         // padded K for stage2 MMA

// ---------------- scratch (device globals; no allocs allowed) ----------------
__device__ float         g_hpre[BDIM * HDIM];           // 512x300
__device__ float         g_P[BDIM * 64];                // cols 0..49 = nb@sbeta, col 50 = nb@bow_w
__device__ float         g_h2[BDIM * HDIM];
__device__ float         g_theta[BDIM * KDIM];
__device__ __nv_bfloat16 g_thetab16[BDIM * 64];         // zero-padded to K=64
__device__ float         g_kldrow[BDIM];
__device__ float         g_sumexp[BDIM];                // per-row sum of exp(logits)
__device__ float         g_reconrow[BDIM];              // per-row recon sum (atomic accum)
__device__ float         g_gammapart[800];
__device__ float         g_sbetaT[51 * VDIM];           // rows 0..49: (beta*gamma)^T, row 50: bow_w
__device__ __nv_bfloat16 g_betab16[(size_t)VPAD * 64];  // beta rows as bf16, zero-padded

// ---------------- mma helper ----------------
__device__ __forceinline__ void mma_bf16(float* d, const unsigned* a, const unsigned* b) {
    asm volatile(
        "mma.sync.aligned.m16n8k16.row.col.f32.bf16.bf16.f32 "
        "{%0,%1,%2,%3}, {%4,%5,%6,%7}, {%8,%9}, {%0,%1,%2,%3};\n"
        : "+f"(d[0]), "+f"(d[1]), "+f"(d[2]), "+f"(d[3])
        : "r"(a[0]), "r"(a[1]), "r"(a[2]), "r"(a[3]), "r"(b[0]), "r"(b[1]));
}

__device__ __forceinline__ void split_hl(float x, __nv_bfloat16& h, __nv_bfloat16& l) {
    h = __float2bfloat16(x);
    l = __float2bfloat16(x - __bfloat162float(h));
}

// ---------------- prep: zero accumulators, sbetaT, bf16 beta, Sum|gamma| partials ----
__global__ __launch_bounds__(256) void prep_kernel(const float* __restrict__ beta,
                                                   const float* __restrict__ gam,
                                                   const float* __restrict__ bow_w) {
    __shared__ float tile[64][51];
    __shared__ float rs[256];
    int v0 = blockIdx.x * 64;
    int tid = threadIdx.x;

    // grid-stride zeroing (782 blocks x 256 threads = 200192 >= all targets)
    int gtid = blockIdx.x * 256 + tid;
    if (gtid < BDIM * HDIM) g_hpre[gtid] = 0.f;
    if (gtid < BDIM * 64)   g_P[gtid] = 0.f;
    if (gtid < BDIM) { g_sumexp[gtid] = 0.f; g_reconrow[gtid] = 0.f; }

    float asum = 0.f;
    for (int idx = tid; idx < 64 * KDIM; idx += 256) {
        int r = idx / KDIM, c = idx % KDIM;
        int v = v0 + r;
        float s = 0.f;
        if (v < VDIM) {
            float bb = beta[(size_t)v * KDIM + c];
            float gg = gam[(size_t)v * KDIM + c];
            s = bb * gg;
            asum += fabsf(gg);
        }
        tile[r][c] = s;
    }
    // bf16 beta copy, zero-padded to [VPAD][64]
    for (int idx = tid; idx < 64 * 64; idx += 256) {
        int r = idx >> 6, c = idx & 63;
        int v = v0 + r;
        float val = (c < KDIM && v < VDIM) ? beta[(size_t)v * KDIM + c] : 0.f;
        g_betab16[(size_t)(v0 + r) * 64 + c] = __float2bfloat16(val);
    }
    __syncthreads();
    for (int idx = tid; idx < KDIM * 64; idx += 256) {
        int k = idx >> 6, j = idx & 63;
        int v = v0 + j;
        if (v < VDIM) g_sbetaT[(size_t)k * VDIM + v] = tile[j][k];
    }
    for (int j = tid; j < 64; j += 256) {
        int v = v0 + j;
        if (v < VDIM) g_sbetaT[(size_t)50 * VDIM + v] = bow_w[v];
    }
    rs[tid] = asum;
    __syncthreads();
    for (int off = 128; off; off >>= 1) {
        if (tid < off) rs[tid] += rs[tid + off];
        __syncthreads();
    }
    if (tid == 0) g_gammapart[blockIdx.x] = rs[0];
}

// =====================================================================
// Fused big GEMM: [hpre | P] = nb @ [W1 | sbetaT]^T      (R11 champion)
// A single bf16, B hi/lo split (2 MMAs). split-K x24.
// BNT=128 as TWO 64-wide halves sharing one sA load per stage.
// 8 warps / 256 threads. Dynamic smem 61.4KB.
// =====================================================================
#define BM 128
#define BNT 128
#define BK 32
#define SPLIT_LEN 2112          // 66 * 32 ; 24 splits cover 50688 >= 50000
#define NSTAGES (SPLIT_LEN / BK)
#define GB_SEG (2 * 128 * 40)   // bf16 elements per operand buffer
#define GB_SMEM_BYTES (3 * GB_SEG * 2)

__global__ __launch_bounds__(256) void gemm_big_kernel(const float* __restrict__ A,
                                                       const float* __restrict__ W1) {
    extern __shared__ __nv_bfloat16 dsm[];
#define SA_(buf,r,k)  dsm[((buf) * 128 + (r)) * 40 + (k)]
#define SBH_(buf,r,k) dsm[GB_SEG + ((buf) * 128 + (r)) * 40 + (k)]
#define SBL_(buf,r,k) dsm[2 * GB_SEG + ((buf) * 128 + (r)) * 40 + (k)]

    const int tid = threadIdx.x;
    const int m0 = blockIdx.x * BM;
    const int n0 = blockIdx.y * BNT;
    const int kstart = blockIdx.z * SPLIT_LEN;

    const int warpId = tid >> 5, lane = tid & 31;
    const int wm = warpId >> 1, wn = warpId & 1;
    const int g = lane >> 2, t = lane & 3;

    float acc[2][2][4][4];
#pragma unroll
    for (int hf = 0; hf < 2; hf++)
#pragma unroll
        for (int mi = 0; mi < 2; mi++)
#pragma unroll
            for (int ni = 0; ni < 4; ni++)
#pragma unroll
                for (int e = 0; e < 4; e++) acc[hf][mi][ni][e] = 0.f;

    float4 ra[4], rb[4];

    auto ldA = [&](int stage) {
        int kb = kstart + stage * BK;
#pragma unroll
        for (int q = 0; q < 4; q++) {
            int qi = tid + q * 256;
            int r = qi >> 3;
            int k = kb + (qi & 7) * 4;
            float4 v = make_float4(0.f, 0.f, 0.f, 0.f);
            if (k < VDIM) v = *reinterpret_cast<const float4*>(A + (size_t)(m0 + r) * VDIM + k);
            ra[q] = v;
        }
    };
    auto ldB = [&](int stage) {
        int kb = kstart + stage * BK;
#pragma unroll
        for (int q = 0; q < 4; q++) {
            int qi = tid + q * 256;
            int r = qi >> 3;
            int k = kb + (qi & 7) * 4;
            int n = n0 + r;
            float4 v = make_float4(0.f, 0.f, 0.f, 0.f);
            if (k < VDIM && n < NTOT) {
                const float* src = (n < HDIM) ? (W1 + (size_t)n * VDIM)
                                              : (g_sbetaT + (size_t)(n - HDIM) * VDIM);
                v = *reinterpret_cast<const float4*>(src + k);
            }
            rb[q] = v;
        }
    };
    auto stAB = [&](int buf) {
#pragma unroll
        for (int q = 0; q < 4; q++) {
            int qi = tid + q * 256;
            int r = qi >> 3;
            int kq = (qi & 7) * 4;
            SA_(buf, r, kq)     = __float2bfloat16(ra[q].x);
            SA_(buf, r, kq + 1) = __float2bfloat16(ra[q].y);
            SA_(buf, r, kq + 2) = __float2bfloat16(ra[q].z);
            SA_(buf, r, kq + 3) = __float2bfloat16(ra[q].w);
        }
#pragma unroll
        for (int q = 0; q < 4; q++) {
            int qi = tid + q * 256;
            int r = qi >> 3;
            int kq = (qi & 7) * 4;
            const float* pv = &rb[q].x;
#pragma unroll
            for (int e = 0; e < 4; e++) {
                __nv_bfloat16 h, l;
                split_hl(pv[e], h, l);
                SBH_(buf, r, kq + e) = h;
                SBL_(buf, r, kq + e) = l;
            }
        }
    };
    auto compute = [&](int buf) {
#pragma unroll
        for (int kk = 0; kk < BK; kk += 16) {
            unsigned af[2][4];
#pragma unroll
            for (int mi = 0; mi < 2; mi++) {
                int r = wm * 32 + mi * 16 + g;
                af[mi][0] = *reinterpret_cast<const unsigned*>(&SA_(buf, r, kk + 2 * t));
                af[mi][1] = *reinterpret_cast<const unsigned*>(&SA_(buf, r + 8, kk + 2 * t));
                af[mi][2] = *reinterpret_cast<const unsigned*>(&SA_(buf, r, kk + 8 + 2 * t));
                af[mi][3] = *reinterpret_cast<const unsigned*>(&SA_(buf, r + 8, kk + 8 + 2 * t));
            }
#pragma unroll
            for (int hf = 0; hf < 2; hf++) {
                unsigned bh[4][2], bl[4][2];
#pragma unroll
                for (int ni = 0; ni < 4; ni++) {
                    int n = hf * 64 + wn * 32 + ni * 8 + g;
                    bh[ni][0] = *reinterpret_cast<const unsigned*>(&SBH_(buf, n, kk + 2 * t));
                    bh[ni][1] = *reinterpret_cast<const unsigned*>(&SBH_(buf, n, kk + 8 + 2 * t));
                    bl[ni][0] = *reinterpret_cast<const unsigned*>(&SBL_(buf, n, kk + 2 * t));
                    bl[ni][1] = *reinterpret_cast<const unsigned*>(&SBL_(buf, n, kk + 8 + 2 * t));
                }
#pragma unroll
                for (int mi = 0; mi < 2; mi++)
#pragma unroll
                    for (int ni = 0; ni < 4; ni++) {
                        mma_bf16(acc[hf][mi][ni], af[mi], bh[ni]);
                        mma_bf16(acc[hf][mi][ni], af[mi], bl[ni]);
                    }
            }
        }
    };

    ldA(0); ldB(0);
    stAB(0);
    __syncthreads();
    for (int s = 0; s < NSTAGES; s++) {
        int cur = s & 1;
        if (s + 1 < NSTAGES) { ldA(s + 1); ldB(s + 1); }
        compute(cur);
        if (s + 1 < NSTAGES) {
            __syncthreads();
            stAB(cur ^ 1);
            __syncthreads();
        }
    }

#pragma unroll
    for (int hf = 0; hf < 2; hf++)
#pragma unroll
        for (int mi = 0; mi < 2; mi++)
#pragma unroll
            for (int ni = 0; ni < 4; ni++)
#pragma unroll
                for (int e = 0; e < 4; e++) {
                    int row = m0 + wm * 32 + mi * 16 + g + ((e >= 2) ? 8 : 0);
                    int col = n0 + hf * 64 + wn * 32 + ni * 8 + 2 * t + (e & 1);
                    float v = acc[hf][mi][ni][e];
                    if (col < HDIM) atomicAdd(&g_hpre[row * HDIM + col], v);
                    else if (col < NTOT) atomicAdd(&g_P[row * 64 + (col - HDIM)], v);
                }
#undef SA_
#undef SBH_
#undef SBL_
}

// =====================================================================
// stage2 (bn1 fused): h2 = bn2(relu( bn1(relu(hpre+b1)) @ W2^T + b2 ))
// BM=64, BNT=32, grid (8,10)=80 blocks, 8 warps as 2(m) x 4(n).
// =====================================================================
#define S2BM 64
#define S2BNT 32
#define S2_NSTAGES (S2_KPAD / BK)   // 10

__global__ __launch_bounds__(256) void stage2_mma_kernel(
    const float* __restrict__ b1_, const float* __restrict__ bn1g,
    const float* __restrict__ bn1b, const float* __restrict__ bn1m,
    const float* __restrict__ bn1v,
    const float* __restrict__ W2, const float* __restrict__ b2,
    const float* __restrict__ bn2g, const float* __restrict__ bn2b,
    const float* __restrict__ bn2m, const float* __restrict__ bn2v) {
    __shared__ __nv_bfloat16 sA[2][S2BM][BK + 8];
    __shared__ __nv_bfloat16 sBh[2][S2BNT][BK + 8];
    __shared__ __nv_bfloat16 sBl[2][S2BNT][BK + 8];
    __shared__ float sb1[S2_KPAD], sA1[S2_KPAD], sA0[S2_KPAD];

    const int tid = threadIdx.x;
    const int m0 = blockIdx.x * S2BM;
    const int n0 = blockIdx.y * S2BNT;

    const int warpId = tid >> 5, lane = tid & 31;
    const int wm2 = warpId >> 2, wn2 = warpId & 3;
    const int g = lane >> 2, t = lane & 3;

    for (int c = tid; c < S2_KPAD; c += 256) {
        float s = 0.f, a0 = 0.f, bb = 0.f;
        if (c < HDIM) {
            s = rsqrtf(bn1v[c] + BN_EPS) * bn1g[c];
            a0 = bn1b[c] - bn1m[c] * s;
            bb = b1_[c];
        }
        sb1[c] = bb; sA1[c] = s; sA0[c] = a0;
    }
    __syncthreads();

    float acc[2][4];
#pragma unroll
    for (int mi = 0; mi < 2; mi++)
#pragma unroll
        for (int e = 0; e < 4; e++) acc[mi][e] = 0.f;

    float4 ra[2], rb;

    auto ldA = [&](int stage) {
        int kb = stage * BK;
#pragma unroll
        for (int q = 0; q < 2; q++) {
            int qi = tid + q * 256;
            int r = qi >> 3;
            int kq = (qi & 7) * 4;
            int k = kb + kq;
            float4 v = make_float4(0.f, 0.f, 0.f, 0.f);
            if (k < HDIM) v = *reinterpret_cast<const float4*>(g_hpre + (m0 + r) * HDIM + k);
            float* pv = &v.x;
#pragma unroll
            for (int e = 0; e < 4; e++) {
                float val = fmaxf(pv[e] + sb1[k + e], 0.f);
                pv[e] = val * sA1[k + e] + sA0[k + e];
            }
            ra[q] = v;
        }
    };
    auto ldB = [&](int stage) {
        int kb = stage * BK;
        int r = tid >> 3;
        int kq = (tid & 7) * 4;
        int k = kb + kq;
        int n = n0 + r;
        float4 v = make_float4(0.f, 0.f, 0.f, 0.f);
        if (k < HDIM && n < HDIM) v = *reinterpret_cast<const float4*>(W2 + (size_t)n * HDIM + k);
        rb = v;
    };
    auto stAB = [&](int buf) {
#pragma unroll
        for (int q = 0; q < 2; q++) {
            int qi = tid + q * 256;
            int r = qi >> 3;
            int kq = (qi & 7) * 4;
            sA[buf][r][kq]     = __float2bfloat16(ra[q].x);
            sA[buf][r][kq + 1] = __float2bfloat16(ra[q].y);
            sA[buf][r][kq + 2] = __float2bfloat16(ra[q].z);
            sA[buf][r][kq + 3] = __float2bfloat16(ra[q].w);
        }
        {
            int r = tid >> 3;
            int kq = (tid & 7) * 4;
            const float* pv = &rb.x;
#pragma unroll
            for (int e = 0; e < 4; e++) {
                __nv_bfloat16 h, l;
                split_hl(pv[e], h, l);
                sBh[buf][r][kq + e] = h;
                sBl[buf][r][kq + e] = l;
            }
        }
    };
    auto compute = [&](int buf) {
#pragma unroll
        for (int kk = 0; kk < BK; kk += 16) {
            unsigned af[2][4], bh[2], bl[2];
#pragma unroll
            for (int mi = 0; mi < 2; mi++) {
                int r = wm2 * 32 + mi * 16 + g;
                af[mi][0] = *reinterpret_cast<const unsigned*>(&sA[buf][r][kk + 2 * t]);
                af[mi][1] = *reinterpret_cast<const unsigned*>(&sA[buf][r + 8][kk + 2 * t]);
                af[mi][2] = *reinterpret_cast<const unsigned*>(&sA[buf][r][kk + 8 + 2 * t]);
                af[mi][3] = *reinterpret_cast<const unsigned*>(&sA[buf][r + 8][kk + 8 + 2 * t]);
            }
            {
                int n = wn2 * 8 + g;
                bh[0] = *reinterpret_cast<const unsigned*>(&sBh[buf][n][kk + 2 * t]);
                bh[1] = *reinterpret_cast<const unsigned*>(&sBh[buf][n][kk + 8 + 2 * t]);
                bl[0] = *reinterpret_cast<const unsigned*>(&sBl[buf][n][kk + 2 * t]);
                bl[1] = *reinterpret_cast<const unsigned*>(&sBl[buf][n][kk + 8 + 2 * t]);
            }
#pragma unroll
            for (int mi = 0; mi < 2; mi++) {
                mma_bf16(acc[mi], af[mi], bh);
                mma_bf16(acc[mi], af[mi], bl);
            }
        }
    };

    ldA(0); ldB(0);
    stAB(0);
    __syncthreads();
    for (int s = 0; s < S2_NSTAGES; s++) {
        int cur = s & 1;
        if (s + 1 < S2_NSTAGES) { ldA(s + 1); ldB(s + 1); }
        compute(cur);
        if (s + 1 < S2_NSTAGES) {
            __syncthreads();
            stAB(cur ^ 1);
            __syncthreads();
        }
    }

#pragma unroll
    for (int mi = 0; mi < 2; mi++)
#pragma unroll
        for (int e = 0; e < 4; e++) {
            int row = m0 + wm2 * 32 + mi * 16 + g + ((e >= 2) ? 8 : 0);
            int col = n0 + wn2 * 8 + 2 * t + (e & 1);
            if (col < HDIM) {
                float x = fmaxf(acc[mi][e] + b2[col], 0.f);
                x = (x - bn2m[col]) * rsqrtf(bn2v[col] + BN_EPS) * bn2g[col] + bn2b[col];
                g_h2[row * HDIM + col] = x;
            }
        }
}

// =====================================================================
// stage3 (REWRITTEN): warp-per-row. Coalesced muW/lsW reads,
// warp-parallel softmax/theta/kld. All fp32.
// grid 128 x 128 threads (4 warps/block, 1 row per warp).
// =====================================================================
__global__ __launch_bounds__(128) void stage3_kernel(const float* __restrict__ muW,
                                                     const float* __restrict__ mub,
                                                     const float* __restrict__ lsW,
                                                     const float* __restrict__ lsb) {
    __shared__ float smu[4][52];
    __shared__ float sls[4][52];
    const int w = threadIdx.x >> 5, lane = threadIdx.x & 31;
    const int b = blockIdx.x * 4 + w;

    // h row into registers (lane-strided, coalesced)
    float hreg[10];
#pragma unroll
    for (int i = 0; i < 10; i++) {
        int j = lane + 32 * i;
        hreg[i] = (j < HDIM) ? g_h2[b * HDIM + j] : 0.f;
    }

    for (int k = 0; k < KDIM; k++) {
        const float* mw = muW + (size_t)k * HDIM;
        const float* lw = lsW + (size_t)k * HDIM;
        float mu = 0.f, ls = 0.f;
#pragma unroll
        for (int i = 0; i < 10; i++) {
            int j = lane + 32 * i;
            if (j < HDIM) {
                mu += hreg[i] * mw[j];
                ls += hreg[i] * lw[j];
            }
        }
#pragma unroll
        for (int off = 16; off; off >>= 1) {
            mu += __shfl_xor_sync(0xffffffffu, mu, off);
            ls += __shfl_xor_sync(0xffffffffu, ls, off);
        }
        if (lane == 0) {
            smu[w][k] = mu + mub[k];
            sls[w][k] = ls + lsb[k];
        }
    }
    __syncwarp();

    // softmax + kld: lanes cover k=lane and k=lane+32
    float mu1 = (lane < KDIM) ? smu[w][lane] : -1e30f;
    float mu2 = (lane + 32 < KDIM) ? smu[w][lane + 32] : -1e30f;
    float mx = fmaxf(mu1, mu2);
#pragma unroll
    for (int off = 16; off; off >>= 1) mx = fmaxf(mx, __shfl_xor_sync(0xffffffffu, mx, off));
    float e1 = (lane < KDIM) ? __expf(mu1 - mx) : 0.f;
    float e2 = (lane + 32 < KDIM) ? __expf(mu2 - mx) : 0.f;
    float s = e1 + e2;
#pragma unroll
    for (int off = 16; off; off >>= 1) s += __shfl_xor_sync(0xffffffffu, s, off);
    float inv = 1.f / s;

    float kldp = 0.f;
    if (lane < KDIM) {   // always true (lane<32<50)
        float ls1 = sls[w][lane];
        kldp += 1.f + ls1 - mu1 * mu1 - __expf(ls1);
        float th = e1 * inv;
        g_theta[b * KDIM + lane] = th;
        g_thetab16[b * 64 + lane] = __float2bfloat16(th);
    }
    if (lane + 32 < KDIM) {
        float ls2 = sls[w][lane + 32];
        kldp += 1.f + ls2 - mu2 * mu2 - __expf(ls2);
        float th = e2 * inv;
        g_theta[b * KDIM + lane + 32] = th;
        g_thetab16[b * 64 + lane + 32] = __float2bfloat16(th);
    } else {
        g_thetab16[b * 64 + lane + 32] = __float2bfloat16(0.f);
    }
#pragma unroll
    for (int off = 16; off; off >>= 1) kldp += __shfl_xor_sync(0xffffffffu, kldp, off);
    if (lane == 0) g_kldrow[b] = kldp;
}

// =====================================================================
// Softmax passes: recompute logits tiles; sB from precomputed bf16 beta.
// =====================================================================
#define SOFTMAX_TILE_PROLOGUE                                                              \
    __shared__ __nv_bfloat16 sA[128][72];                                                  \
    __shared__ __nv_bfloat16 sB[128][72];                                                  \
    __shared__ float s_sum[128];                                                           \
    int tid = threadIdx.x;                                                                 \
    int m0 = blockIdx.x * 128, v0 = blockIdx.y * 128;                                      \
    for (int i = tid; i < 128; i += 256) s_sum[i] = 0.f;                                   \
    _Pragma("unroll")                                                                      \
    for (int q = 0; q < 4; q++) {                                                          \
        int qi = tid + q * 256;                                                            \
        int r = qi >> 3;                                                                   \
        int c8 = (qi & 7) * 8;                                                             \
        uint4 u = *reinterpret_cast<const uint4*>(&g_thetab16[(m0 + r) * 64 + c8]);        \
        *reinterpret_cast<uint4*>(&sA[r][c8]) = u;                                         \
        uint4 ub = *reinterpret_cast<const uint4*>(&g_betab16[(size_t)(v0 + r) * 64 + c8]);\
        *reinterpret_cast<uint4*>(&sB[r][c8]) = ub;                                        \
    }                                                                                      \
    __syncthreads();                                                                       \
    const int warpId = tid >> 5, lane = tid & 31;                                          \
    const int wm = warpId >> 1, wn = warpId & 1;                                           \
    const int g = lane >> 2, t = lane & 3;                                                 \
    float acc[2][8][4];                                                                    \
    _Pragma("unroll")                                                                      \
    for (int mi = 0; mi < 2; mi++)                                                         \
        _Pragma("unroll")                                                                  \
        for (int ni = 0; ni < 8; ni++)                                                     \
            _Pragma("unroll")                                                              \
            for (int e = 0; e < 4; e++) acc[mi][ni][e] = 0.f;                              \
    _Pragma("unroll")                                                                      \
    for (int kk = 0; kk < 64; kk += 16) {                                                  \
        unsigned af[2][4], bfr[8][2];                                                      \
        _Pragma("unroll")                                                                  \
        for (int mi = 0; mi < 2; mi++) {                                                   \
            int r = wm * 32 + mi * 16 + g;                                                 \
            af[mi][0] = *reinterpret_cast<const unsigned*>(&sA[r][kk + 2 * t]);            \
            af[mi][1] = *reinterpret_cast<const unsigned*>(&sA[r + 8][kk + 2 * t]);        \
            af[mi][2] = *reinterpret_cast<const unsigned*>(&sA[r][kk + 8 + 2 * t]);        \
            af[mi][3] = *reinterpret_cast<const unsigned*>(&sA[r + 8][kk + 8 + 2 * t]);    \
        }                                                                                  \
        _Pragma("unroll")                                                                  \
        for (int ni = 0; ni < 8; ni++) {                                                   \
            int n = wn * 64 + ni * 8 + g;                                                  \
            bfr[ni][0] = *reinterpret_cast<const unsigned*>(&sB[n][kk + 2 * t]);           \
            bfr[ni][1] = *reinterpret_cast<const unsigned*>(&sB[n][kk + 8 + 2 * t]);       \
        }                                                                                  \
        _Pragma("unroll")                                                                  \
        for (int mi = 0; mi < 2; mi++)                                                     \
            _Pragma("unroll")                                                              \
            for (int ni = 0; ni < 8; ni++) mma_bf16(acc[mi][ni], af[mi], bfr[ni]);         \
    }

__global__ __launch_bounds__(256) void softmax_sum_kernel(const float* __restrict__ base_rates) {
    SOFTMAX_TILE_PROLOGUE

    float ps[2][2] = {{0.f, 0.f}, {0.f, 0.f}};
#pragma unroll
    for (int mi = 0; mi < 2; mi++)
#pragma unroll
        for (int ni = 0; ni < 8; ni++) {
            int v = v0 + wn * 64 + ni * 8 + 2 * t;
            if (v < VDIM) {
                float br0 = base_rates[v], br1 = base_rates[v + 1];
                ps[mi][0] += __expf(acc[mi][ni][0] + br0) + __expf(acc[mi][ni][1] + br1);
                ps[mi][1] += __expf(acc[mi][ni][2] + br0) + __expf(acc[mi][ni][3] + br1);
            }
        }
#pragma unroll
    for (int mi = 0; mi < 2; mi++)
#pragma unroll
        for (int hh = 0; hh < 2; hh++) {
            float v = ps[mi][hh];
            v += __shfl_xor_sync(0xffffffffu, v, 1);
            v += __shfl_xor_sync(0xffffffffu, v, 2);
            if (t == 0) atomicAdd(&s_sum[wm * 32 + mi * 16 + g + hh * 8], v);
        }
    __syncthreads();
    if (tid < 128) atomicAdd(&g_sumexp[m0 + tid], s_sum[tid]);
}

__global__ __launch_bounds__(256) void recon_kernel(const float* __restrict__ base_rates,
                                                    const float* __restrict__ bows) {
    SOFTMAX_TILE_PROLOGUE

    float ps[2][2] = {{0.f, 0.f}, {0.f, 0.f}};
    float cS[2][2], lS[2][2];
#pragma unroll
    for (int mi = 0; mi < 2; mi++)
#pragma unroll
        for (int hh = 0; hh < 2; hh++) {
            float s = g_sumexp[m0 + wm * 32 + mi * 16 + g + hh * 8];
            cS[mi][hh] = 1e-6f * s;
            lS[mi][hh] = __logf(s);
        }
#pragma unroll
    for (int mi = 0; mi < 2; mi++)
#pragma unroll
        for (int ni = 0; ni < 8; ni++) {
            int v = v0 + wn * 64 + ni * 8 + 2 * t;
            if (v < VDIM) {
                float br0 = base_rates[v], br1 = base_rates[v + 1];
                int r1 = m0 + wm * 32 + mi * 16 + g;
                float2 bw1 = *reinterpret_cast<const float2*>(bows + (size_t)r1 * VDIM + v);
                float2 bw2 = *reinterpret_cast<const float2*>(bows + (size_t)(r1 + 8) * VDIM + v);
                ps[mi][0] += (__logf(__expf(acc[mi][ni][0] + br0) + cS[mi][0]) - lS[mi][0]) * bw1.x
                           + (__logf(__expf(acc[mi][ni][1] + br1) + cS[mi][0]) - lS[mi][0]) * bw1.y;
                ps[mi][1] += (__logf(__expf(acc[mi][ni][2] + br0) + cS[mi][1]) - lS[mi][1]) * bw2.x
                           + (__logf(__expf(acc[mi][ni][3] + br1) + cS[mi][1]) - lS[mi][1]) * bw2.y;
            }
        }
#pragma unroll
    for (int mi = 0; mi < 2; mi++)
#pragma unroll
        for (int hh = 0; hh < 2; hh++) {
            float v = ps[mi][hh];
            v += __shfl_xor_sync(0xffffffffu, v, 1);
            v += __shfl_xor_sync(0xffffffffu, v, 2);
            if (t == 0) atomicAdd(&s_sum[wm * 32 + mi * 16 + g + hh * 8], v);
        }
    __syncthreads();
    if (tid < 128) atomicAdd(&g_reconrow[m0 + tid], s_sum[tid]);
}

// ---------------- final deterministic reduction ----------------
__device__ float block_sum256(float x, float* red) {
    int tid = threadIdx.x;
    red[tid] = x;
    __syncthreads();
    for (int off = 128; off; off >>= 1) {
        if (tid < off) red[tid] += red[tid + off];
        __syncthreads();
    }
    float r = red[0];
    __syncthreads();
    return r;
}

__global__ void final_kernel(const float* __restrict__ labels, const float* __restrict__ base_rates,
                             const float* __restrict__ bow_w, const float* __restrict__ topic_w,
                             const float* __restrict__ bow_b, const float* __restrict__ topic_b,
                             float* __restrict__ out, int n_gamma_parts) {
    __shared__ float red[256];
    int tid = threadIdx.x;
    float sumRecon = 0.f, sumKld = 0.f, sumMse = 0.f, sumBase = 0.f, sumBw2 = 0.f, sumGam = 0.f;
    for (int b = tid; b < BDIM; b += 256) {
        sumRecon += g_reconrow[b];
        sumKld += g_kldrow[b];
        float pred = bow_b[0] + topic_b[0] + g_P[b * 64 + 50];
        for (int k = 0; k < KDIM; k++) {
            float th = g_theta[b * KDIM + k];
            pred += th * (g_P[b * 64 + k] + topic_w[k]);
        }
        float d = pred - labels[b];
        sumMse += d * d;
    }
    for (int v = tid; v < VDIM; v += 256) {
        sumBase += fabsf(base_rates[v]);
        float w = bow_w[v];
        sumBw2 += w * w;
    }
    for (int i = tid; i < n_gamma_parts; i += 256) sumGam += g_gammapart[i];

    float sr = block_sum256(sumRecon, red);
    float sk = block_sum256(sumKld, red);
    float sm = block_sum256(sumMse, red);
    float sb = block_sum256(sumBase, red);
    float sw2 = block_sum256(sumBw2, red);
    float sg = block_sum256(sumGam, red);
    if (tid == 0) {
        out[0] = -sr / (float)BDIM;
        out[1] = 0.0005f * sb + sm / (float)BDIM + 0.000005f * sg + 0.0005f * sqrtf(sw2);
        out[2] = -0.5f * sk / (float)BDIM;
    }
}

// ---------------- launch ----------------
extern "C" void kernel_launch(void* const* d_in, const int* in_sizes, int n_in,
                              void* d_out, int out_size) {
    const float* bows    = (const float*)d_in[0];
    const float* nb      = (const float*)d_in[1];
    const float* labels  = (const float*)d_in[2];
    const float* W1      = (const float*)d_in[3];
    const float* b1      = (const float*)d_in[4];
    const float* W2      = (const float*)d_in[5];
    const float* b2      = (const float*)d_in[6];
    const float* bn1g    = (const float*)d_in[7];
    const float* bn1b    = (const float*)d_in[8];
    const float* bn1m    = (const float*)d_in[9];
    const float* bn1v    = (const float*)d_in[10];
    const float* bn2g    = (const float*)d_in[11];
    const float* bn2b    = (const float*)d_in[12];
    const float* bn2m    = (const float*)d_in[13];
    const float* bn2v    = (const float*)d_in[14];
    const float* muW     = (const float*)d_in[15];
    const float* mub     = (const float*)d_in[16];
    const float* lsW     = (const float*)d_in[17];
    const float* lsb     = (const float*)d_in[18];
    const float* beta    = (const float*)d_in[19];
    const float* gam     = (const float*)d_in[20];
    const float* base    = (const float*)d_in[21];
    const float* bow_w   = (const float*)d_in[22];
    const float* bow_b   = (const float*)d_in[23];
    const float* topic_w = (const float*)d_in[24];
    const float* topic_b = (const float*)d_in[25];
    float* out = (float*)d_out;

    const int nGammaBlocks = (VDIM + 63) / 64;  // 782
    const int nVBlocks = (VDIM + 127) / 128;    // 391

    // attribute set only (no allocation) — needed for 61.4KB dynamic smem
    cudaFuncSetAttribute(gemm_big_kernel,
                         cudaFuncAttributeMaxDynamicSharedMemorySize, GB_SMEM_BYTES);

    prep_kernel<<<nGammaBlocks, 256>>>(beta, gam, bow_w);
    gemm_big_kernel<<<dim3(BDIM / BM, (NTOT + BNT - 1) / BNT, 24), 256, GB_SMEM_BYTES>>>(nb, W1);
    stage2_mma_kernel<<<dim3(BDIM / S2BM, (HDIM + S2BNT - 1) / S2BNT), 256>>>(
        b1, bn1g, bn1b, bn1m, bn1v, W2, b2, bn2g, bn2b, bn2m, bn2v);
    stage3_kernel<<<BDIM / 4, 128>>>(muW, mub, lsW, lsb);
    softmax_sum_kernel<<<dim3(BDIM / 128, nVBlocks), 256>>>(base);
    recon_kernel<<<dim3(BDIM / 128, nVBlocks), 256>>>(base, bows);
    final_kernel<<<1, 256>>>(labels, base, bow_w, topic_w, bow_b, topic_b, out, nGammaBlocks);
}

// round 15
// speedup vs baseline: 1.1749x; 1.1749x over previous
#include <cuda_runtime.h>
#include <cuda_bf16.h>
#include <cstdint>

// ---------------- problem constants ----------------
#define VDIM 50000
#define VPAD 50048          // 782*64, padded for bf16 beta array
#define KDIM 50
#define HDIM 300
#define BDIM 512
#define NTOT 351            // 300 (W1 cols) + 51 (sbeta/bow_w cols)
#define BN_EPS 1e-5f
#define S2_KPAD 320         // padded K for stage2 MMA

// ---------------- scratch (device globals; no allocs allowed) ----------------
__device__ float         g_hpre[BDIM * HDIM];           // 512x300
__device__ float         g_P[BDIM * 64];                // cols 0..49 = nb@sbeta, col 50 = nb@bow_w
__device__ float         g_h2[BDIM * HDIM];
__device__ float         g_theta[BDIM * KDIM];
__device__ __nv_bfloat16 g_thetab16[BDIM * 64];         // zero-padded to K=64
__device__ float         g_kldrow[BDIM];
__device__ float         g_sumexp[BDIM];                // per-row sum of exp(logits)
__device__ float         g_reconrow[BDIM];              // per-row recon sum (atomic accum)
__device__ float         g_gammapart[800];
__device__ float         g_sbetaT[51 * VDIM];           // rows 0..49: (beta*gamma)^T, row 50: bow_w
__device__ __nv_bfloat16 g_betab16[(size_t)VPAD * 64];  // beta rows as bf16, zero-padded
__device__ float         g_muWT[HDIM * KDIM];           // muW transposed [j][k]
__device__ float         g_lsWT[HDIM * KDIM];           // lsW transposed [j][k]

// ---------------- mma helper ----------------
__device__ __forceinline__ void mma_bf16(float* d, const unsigned* a, const unsigned* b) {
    asm volatile(
        "mma.sync.aligned.m16n8k16.row.col.f32.bf16.bf16.f32 "
        "{%0,%1,%2,%3}, {%4,%5,%6,%7}, {%8,%9}, {%0,%1,%2,%3};\n"
        : "+f"(d[0]), "+f"(d[1]), "+f"(d[2]), "+f"(d[3])
        : "r"(a[0]), "r"(a[1]), "r"(a[2]), "r"(a[3]), "r"(b[0]), "r"(b[1]));
}

__device__ __forceinline__ void split_hl(float x, __nv_bfloat16& h, __nv_bfloat16& l) {
    h = __float2bfloat16(x);
    l = __float2bfloat16(x - __bfloat162float(h));
}

// ---------------- prep: zeroing, sbetaT, bf16 beta, muW/lsW transpose, Sum|gamma| ----
__global__ __launch_bounds__(256) void prep_kernel(const float* __restrict__ beta,
                                                   const float* __restrict__ gam,
                                                   const float* __restrict__ bow_w,
                                                   const float* __restrict__ muW,
                                                   const float* __restrict__ lsW) {
    __shared__ float tile[64][51];
    __shared__ float rs[256];
    int v0 = blockIdx.x * 64;
    int tid = threadIdx.x;

    // grid-stride zeroing + weight transpose (782 blocks x 256 = 200192 threads)
    int gtid = blockIdx.x * 256 + tid;
    if (gtid < BDIM * HDIM) g_hpre[gtid] = 0.f;
    if (gtid < BDIM * 64)   g_P[gtid] = 0.f;
    if (gtid < BDIM) { g_sumexp[gtid] = 0.f; g_reconrow[gtid] = 0.f; }
    if (gtid < KDIM * HDIM) {
        int k = gtid / HDIM, j = gtid - k * HDIM;
        g_muWT[j * KDIM + k] = muW[gtid];
        g_lsWT[j * KDIM + k] = lsW[gtid];
    }

    float asum = 0.f;
    for (int idx = tid; idx < 64 * KDIM; idx += 256) {
        int r = idx / KDIM, c = idx % KDIM;
        int v = v0 + r;
        float s = 0.f;
        if (v < VDIM) {
            float bb = beta[(size_t)v * KDIM + c];
            float gg = gam[(size_t)v * KDIM + c];
            s = bb * gg;
            asum += fabsf(gg);
        }
        tile[r][c] = s;
    }
    // bf16 beta copy, zero-padded to [VPAD][64]
    for (int idx = tid; idx < 64 * 64; idx += 256) {
        int r = idx >> 6, c = idx & 63;
        int v = v0 + r;
        float val = (c < KDIM && v < VDIM) ? beta[(size_t)v * KDIM + c] : 0.f;
        g_betab16[(size_t)(v0 + r) * 64 + c] = __float2bfloat16(val);
    }
    __syncthreads();
    for (int idx = tid; idx < KDIM * 64; idx += 256) {
        int k = idx >> 6, j = idx & 63;
        int v = v0 + j;
        if (v < VDIM) g_sbetaT[(size_t)k * VDIM + v] = tile[j][k];
    }
    for (int j = tid; j < 64; j += 256) {
        int v = v0 + j;
        if (v < VDIM) g_sbetaT[(size_t)50 * VDIM + v] = bow_w[v];
    }
    rs[tid] = asum;
    __syncthreads();
    for (int off = 128; off; off >>= 1) {
        if (tid < off) rs[tid] += rs[tid + off];
        __syncthreads();
    }
    if (tid == 0) g_gammapart[blockIdx.x] = rs[0];
}

// =====================================================================
// Fused big GEMM: [hpre | P] = nb @ [W1 | sbetaT]^T      (R11 champion)
// =====================================================================
#define BM 128
#define BNT 128
#define BK 32
#define SPLIT_LEN 2112          // 66 * 32 ; 24 splits cover 50688 >= 50000
#define NSTAGES (SPLIT_LEN / BK)
#define GB_SEG (2 * 128 * 40)   // bf16 elements per operand buffer
#define GB_SMEM_BYTES (3 * GB_SEG * 2)

__global__ __launch_bounds__(256) void gemm_big_kernel(const float* __restrict__ A,
                                                       const float* __restrict__ W1) {
    extern __shared__ __nv_bfloat16 dsm[];
#define SA_(buf,r,k)  dsm[((buf) * 128 + (r)) * 40 + (k)]
#define SBH_(buf,r,k) dsm[GB_SEG + ((buf) * 128 + (r)) * 40 + (k)]
#define SBL_(buf,r,k) dsm[2 * GB_SEG + ((buf) * 128 + (r)) * 40 + (k)]

    const int tid = threadIdx.x;
    const int m0 = blockIdx.x * BM;
    const int n0 = blockIdx.y * BNT;
    const int kstart = blockIdx.z * SPLIT_LEN;

    const int warpId = tid >> 5, lane = tid & 31;
    const int wm = warpId >> 1, wn = warpId & 1;
    const int g = lane >> 2, t = lane & 3;

    float acc[2][2][4][4];
#pragma unroll
    for (int hf = 0; hf < 2; hf++)
#pragma unroll
        for (int mi = 0; mi < 2; mi++)
#pragma unroll
            for (int ni = 0; ni < 4; ni++)
#pragma unroll
                for (int e = 0; e < 4; e++) acc[hf][mi][ni][e] = 0.f;

    float4 ra[4], rb[4];

    auto ldA = [&](int stage) {
        int kb = kstart + stage * BK;
#pragma unroll
        for (int q = 0; q < 4; q++) {
            int qi = tid + q * 256;
            int r = qi >> 3;
            int k = kb + (qi & 7) * 4;
            float4 v = make_float4(0.f, 0.f, 0.f, 0.f);
            if (k < VDIM) v = *reinterpret_cast<const float4*>(A + (size_t)(m0 + r) * VDIM + k);
            ra[q] = v;
        }
    };
    auto ldB = [&](int stage) {
        int kb = kstart + stage * BK;
#pragma unroll
        for (int q = 0; q < 4; q++) {
            int qi = tid + q * 256;
            int r = qi >> 3;
            int k = kb + (qi & 7) * 4;
            int n = n0 + r;
            float4 v = make_float4(0.f, 0.f, 0.f, 0.f);
            if (k < VDIM && n < NTOT) {
                const float* src = (n < HDIM) ? (W1 + (size_t)n * VDIM)
                                              : (g_sbetaT + (size_t)(n - HDIM) * VDIM);
                v = *reinterpret_cast<const float4*>(src + k);
            }
            rb[q] = v;
        }
    };
    auto stAB = [&](int buf) {
#pragma unroll
        for (int q = 0; q < 4; q++) {
            int qi = tid + q * 256;
            int r = qi >> 3;
            int kq = (qi & 7) * 4;
            SA_(buf, r, kq)     = __float2bfloat16(ra[q].x);
            SA_(buf, r, kq + 1) = __float2bfloat16(ra[q].y);
            SA_(buf, r, kq + 2) = __float2bfloat16(ra[q].z);
            SA_(buf, r, kq + 3) = __float2bfloat16(ra[q].w);
        }
#pragma unroll
        for (int q = 0; q < 4; q++) {
            int qi = tid + q * 256;
            int r = qi >> 3;
            int kq = (qi & 7) * 4;
            const float* pv = &rb[q].x;
#pragma unroll
            for (int e = 0; e < 4; e++) {
                __nv_bfloat16 h, l;
                split_hl(pv[e], h, l);
                SBH_(buf, r, kq + e) = h;
                SBL_(buf, r, kq + e) = l;
            }
        }
    };
    auto compute = [&](int buf) {
#pragma unroll
        for (int kk = 0; kk < BK; kk += 16) {
            unsigned af[2][4];
#pragma unroll
            for (int mi = 0; mi < 2; mi++) {
                int r = wm * 32 + mi * 16 + g;
                af[mi][0] = *reinterpret_cast<const unsigned*>(&SA_(buf, r, kk + 2 * t));
                af[mi][1] = *reinterpret_cast<const unsigned*>(&SA_(buf, r + 8, kk + 2 * t));
                af[mi][2] = *reinterpret_cast<const unsigned*>(&SA_(buf, r, kk + 8 + 2 * t));
                af[mi][3] = *reinterpret_cast<const unsigned*>(&SA_(buf, r + 8, kk + 8 + 2 * t));
            }
#pragma unroll
            for (int hf = 0; hf < 2; hf++) {
                unsigned bh[4][2], bl[4][2];
#pragma unroll
                for (int ni = 0; ni < 4; ni++) {
                    int n = hf * 64 + wn * 32 + ni * 8 + g;
                    bh[ni][0] = *reinterpret_cast<const unsigned*>(&SBH_(buf, n, kk + 2 * t));
                    bh[ni][1] = *reinterpret_cast<const unsigned*>(&SBH_(buf, n, kk + 8 + 2 * t));
                    bl[ni][0] = *reinterpret_cast<const unsigned*>(&SBL_(buf, n, kk + 2 * t));
                    bl[ni][1] = *reinterpret_cast<const unsigned*>(&SBL_(buf, n, kk + 8 + 2 * t));
                }
#pragma unroll
                for (int mi = 0; mi < 2; mi++)
#pragma unroll
                    for (int ni = 0; ni < 4; ni++) {
                        mma_bf16(acc[hf][mi][ni], af[mi], bh[ni]);
                        mma_bf16(acc[hf][mi][ni], af[mi], bl[ni]);
                    }
            }
        }
    };

    ldA(0); ldB(0);
    stAB(0);
    __syncthreads();
    for (int s = 0; s < NSTAGES; s++) {
        int cur = s & 1;
        if (s + 1 < NSTAGES) { ldA(s + 1); ldB(s + 1); }
        compute(cur);
        if (s + 1 < NSTAGES) {
            __syncthreads();
            stAB(cur ^ 1);
            __syncthreads();
        }
    }

#pragma unroll
    for (int hf = 0; hf < 2; hf++)
#pragma unroll
        for (int mi = 0; mi < 2; mi++)
#pragma unroll
            for (int ni = 0; ni < 4; ni++)
#pragma unroll
                for (int e = 0; e < 4; e++) {
                    int row = m0 + wm * 32 + mi * 16 + g + ((e >= 2) ? 8 : 0);
                    int col = n0 + hf * 64 + wn * 32 + ni * 8 + 2 * t + (e & 1);
                    float v = acc[hf][mi][ni][e];
                    if (col < HDIM) atomicAdd(&g_hpre[row * HDIM + col], v);
                    else if (col < NTOT) atomicAdd(&g_P[row * 64 + (col - HDIM)], v);
                }
#undef SA_
#undef SBH_
#undef SBL_
}

// =====================================================================
// stage2 (bn1 fused): h2 = bn2(relu( bn1(relu(hpre+b1)) @ W2^T + b2 ))
// BM=64, BNT=32, grid (8,10)=80 blocks, 8 warps as 2(m) x 4(n).
// =====================================================================
#define S2BM 64
#define S2BNT 32
#define S2_NSTAGES (S2_KPAD / BK)   // 10

__global__ __launch_bounds__(256) void stage2_mma_kernel(
    const float* __restrict__ b1_, const float* __restrict__ bn1g,
    const float* __restrict__ bn1b, const float* __restrict__ bn1m,
    const float* __restrict__ bn1v,
    const float* __restrict__ W2, const float* __restrict__ b2,
    const float* __restrict__ bn2g, const float* __restrict__ bn2b,
    const float* __restrict__ bn2m, const float* __restrict__ bn2v) {
    __shared__ __nv_bfloat16 sA[2][S2BM][BK + 8];
    __shared__ __nv_bfloat16 sBh[2][S2BNT][BK + 8];
    __shared__ __nv_bfloat16 sBl[2][S2BNT][BK + 8];
    __shared__ float sb1[S2_KPAD], sA1[S2_KPAD], sA0[S2_KPAD];

    const int tid = threadIdx.x;
    const int m0 = blockIdx.x * S2BM;
    const int n0 = blockIdx.y * S2BNT;

    const int warpId = tid >> 5, lane = tid & 31;
    const int wm2 = warpId >> 2, wn2 = warpId & 3;
    const int g = lane >> 2, t = lane & 3;

    for (int c = tid; c < S2_KPAD; c += 256) {
        float s = 0.f, a0 = 0.f, bb = 0.f;
        if (c < HDIM) {
            s = rsqrtf(bn1v[c] + BN_EPS) * bn1g[c];
            a0 = bn1b[c] - bn1m[c] * s;
            bb = b1_[c];
        }
        sb1[c] = bb; sA1[c] = s; sA0[c] = a0;
    }
    __syncthreads();

    float acc[2][4];
#pragma unroll
    for (int mi = 0; mi < 2; mi++)
#pragma unroll
        for (int e = 0; e < 4; e++) acc[mi][e] = 0.f;

    float4 ra[2], rb;

    auto ldA = [&](int stage) {
        int kb = stage * BK;
#pragma unroll
        for (int q = 0; q < 2; q++) {
            int qi = tid + q * 256;
            int r = qi >> 3;
            int kq = (qi & 7) * 4;
            int k = kb + kq;
            float4 v = make_float4(0.f, 0.f, 0.f, 0.f);
            if (k < HDIM) v = *reinterpret_cast<const float4*>(g_hpre + (m0 + r) * HDIM + k);
            float* pv = &v.x;
#pragma unroll
            for (int e = 0; e < 4; e++) {
                float val = fmaxf(pv[e] + sb1[k + e], 0.f);
                pv[e] = val * sA1[k + e] + sA0[k + e];
            }
            ra[q] = v;
        }
    };
    auto ldB = [&](int stage) {
        int kb = stage * BK;
        int r = tid >> 3;
        int kq = (tid & 7) * 4;
        int k = kb + kq;
        int n = n0 + r;
        float4 v = make_float4(0.f, 0.f, 0.f, 0.f);
        if (k < HDIM && n < HDIM) v = *reinterpret_cast<const float4*>(W2 + (size_t)n * HDIM + k);
        rb = v;
    };
    auto stAB = [&](int buf) {
#pragma unroll
        for (int q = 0; q < 2; q++) {
            int qi = tid + q * 256;
            int r = qi >> 3;
            int kq = (qi & 7) * 4;
            sA[buf][r][kq]     = __float2bfloat16(ra[q].x);
            sA[buf][r][kq + 1] = __float2bfloat16(ra[q].y);
            sA[buf][r][kq + 2] = __float2bfloat16(ra[q].z);
            sA[buf][r][kq + 3] = __float2bfloat16(ra[q].w);
        }
        {
            int r = tid >> 3;
            int kq = (tid & 7) * 4;
            const float* pv = &rb.x;
#pragma unroll
            for (int e = 0; e < 4; e++) {
                __nv_bfloat16 h, l;
                split_hl(pv[e], h, l);
                sBh[buf][r][kq + e] = h;
                sBl[buf][r][kq + e] = l;
            }
        }
    };
    auto compute = [&](int buf) {
#pragma unroll
        for (int kk = 0; kk < BK; kk += 16) {
            unsigned af[2][4], bh[2], bl[2];
#pragma unroll
            for (int mi = 0; mi < 2; mi++) {
                int r = wm2 * 32 + mi * 16 + g;
                af[mi][0] = *reinterpret_cast<const unsigned*>(&sA[buf][r][kk + 2 * t]);
                af[mi][1] = *reinterpret_cast<const unsigned*>(&sA[buf][r + 8][kk + 2 * t]);
                af[mi][2] = *reinterpret_cast<const unsigned*>(&sA[buf][r][kk + 8 + 2 * t]);
                af[mi][3] = *reinterpret_cast<const unsigned*>(&sA[buf][r + 8][kk + 8 + 2 * t]);
            }
            {
                int n = wn2 * 8 + g;
                bh[0] = *reinterpret_cast<const unsigned*>(&sBh[buf][n][kk + 2 * t]);
                bh[1] = *reinterpret_cast<const unsigned*>(&sBh[buf][n][kk + 8 + 2 * t]);
                bl[0] = *reinterpret_cast<const unsigned*>(&sBl[buf][n][kk + 2 * t]);
                bl[1] = *reinterpret_cast<const unsigned*>(&sBl[buf][n][kk + 8 + 2 * t]);
            }
#pragma unroll
            for (int mi = 0; mi < 2; mi++) {
                mma_bf16(acc[mi], af[mi], bh);
                mma_bf16(acc[mi], af[mi], bl);
            }
        }
    };

    ldA(0); ldB(0);
    stAB(0);
    __syncthreads();
    for (int s = 0; s < S2_NSTAGES; s++) {
        int cur = s & 1;
        if (s + 1 < S2_NSTAGES) { ldA(s + 1); ldB(s + 1); }
        compute(cur);
        if (s + 1 < S2_NSTAGES) {
            __syncthreads();
            stAB(cur ^ 1);
            __syncthreads();
        }
    }

#pragma unroll
    for (int mi = 0; mi < 2; mi++)
#pragma unroll
        for (int e = 0; e < 4; e++) {
            int row = m0 + wm2 * 32 + mi * 16 + g + ((e >= 2) ? 8 : 0);
            int col = n0 + wn2 * 8 + 2 * t + (e & 1);
            if (col < HDIM) {
                float x = fmaxf(acc[mi][e] + b2[col], 0.f);
                x = (x - bn2m[col]) * rsqrtf(bn2v[col] + BN_EPS) * bn2g[col] + bn2b[col];
                g_h2[row * HDIM + col] = x;
            }
        }
}

// =====================================================================
// stage3 (R12 structure, transposed-weight loads): thread-per-k,
// reads g_muWT[j*50+k] — threads k=0..49 hit consecutive addresses.
// =====================================================================
__global__ void stage3_kernel(const float* __restrict__ mub, const float* __restrict__ lsb) {
    int b = blockIdx.x;
    int tid = threadIdx.x;   // 64 threads
    __shared__ float h[HDIM];
    __shared__ float mus[KDIM];
    __shared__ float klds[64];
    __shared__ float red2[2];
    for (int j = tid; j < HDIM; j += 64) h[j] = g_h2[b * HDIM + j];
    __syncthreads();
    float kld_part = 0.f;
    if (tid < KDIM) {
        float mu = mub[tid], ls = lsb[tid];
#pragma unroll 4
        for (int j = 0; j < HDIM; j++) {
            float hv = h[j];
            mu += hv * g_muWT[j * KDIM + tid];
            ls += hv * g_lsWT[j * KDIM + tid];
        }
        mus[tid] = mu;
        kld_part = 1.f + ls - mu * mu - __expf(ls);
    }
    klds[tid] = (tid < KDIM) ? kld_part : 0.f;
    __syncthreads();
    if (tid == 0) {
        float mx = -1e30f;
        for (int k = 0; k < KDIM; k++) mx = fmaxf(mx, mus[k]);
        float s = 0.f;
        for (int k = 0; k < KDIM; k++) s += __expf(mus[k] - mx);
        red2[0] = mx; red2[1] = s;
        float kk = 0.f;
        for (int k = 0; k < KDIM; k++) kk += klds[k];
        g_kldrow[b] = kk;
    }
    __syncthreads();
    if (tid < KDIM) {
        float th = __expf(mus[tid] - red2[0]) / red2[1];
        g_theta[b * KDIM + tid] = th;
        g_thetab16[b * 64 + tid] = __float2bfloat16(th);
    } else {
        g_thetab16[b * 64 + tid] = __float2bfloat16(0.f);
    }
}

// =====================================================================
// Softmax passes: recompute logits tiles; sB from precomputed bf16 beta.
// =====================================================================
#define SOFTMAX_TILE_PROLOGUE                                                              \
    __shared__ __nv_bfloat16 sA[128][72];                                                  \
    __shared__ __nv_bfloat16 sB[128][72];                                                  \
    __shared__ float s_sum[128];                                                           \
    int tid = threadIdx.x;                                                                 \
    int m0 = blockIdx.x * 128, v0 = blockIdx.y * 128;                                      \
    for (int i = tid; i < 128; i += 256) s_sum[i] = 0.f;                                   \
    _Pragma("unroll")                                                                      \
    for (int q = 0; q < 4; q++) {                                                          \
        int qi = tid + q * 256;                                                            \
        int r = qi >> 3;                                                                   \
        int c8 = (qi & 7) * 8;                                                             \
        uint4 u = *reinterpret_cast<const uint4*>(&g_thetab16[(m0 + r) * 64 + c8]);        \
        *reinterpret_cast<uint4*>(&sA[r][c8]) = u;                                         \
        uint4 ub = *reinterpret_cast<const uint4*>(&g_betab16[(size_t)(v0 + r) * 64 + c8]);\
        *reinterpret_cast<uint4*>(&sB[r][c8]) = ub;                                        \
    }                                                                                      \
    __syncthreads();                                                                       \
    const int warpId = tid >> 5, lane = tid & 31;                                          \
    const int wm = warpId >> 1, wn = warpId & 1;                                           \
    const int g = lane >> 2, t = lane & 3;                                                 \
    float acc[2][8][4];                                                                    \
    _Pragma("unroll")                                                                      \
    for (int mi = 0; mi < 2; mi++)                                                         \
        _Pragma("unroll")                                                                  \
        for (int ni = 0; ni < 8; ni++)                                                     \
            _Pragma("unroll")                                                              \
            for (int e = 0; e < 4; e++) acc[mi][ni][e] = 0.f;                              \
    _Pragma("unroll")                                                                      \
    for (int kk = 0; kk < 64; kk += 16) {                                                  \
        unsigned af[2][4], bfr[8][2];                                                      \
        _Pragma("unroll")                                                                  \
        for (int mi = 0; mi < 2; mi++) {                                                   \
            int r = wm * 32 + mi * 16 + g;                                                 \
            af[mi][0] = *reinterpret_cast<const unsigned*>(&sA[r][kk + 2 * t]);            \
            af[mi][1] = *reinterpret_cast<const unsigned*>(&sA[r + 8][kk + 2 * t]);        \
            af[mi][2] = *reinterpret_cast<const unsigned*>(&sA[r][kk + 8 + 2 * t]);        \
            af[mi][3] = *reinterpret_cast<const unsigned*>(&sA[r + 8][kk + 8 + 2 * t]);    \
        }                                                                                  \
        _Pragma("unroll")                                                                  \
        for (int ni = 0; ni < 8; ni++) {                                                   \
            int n = wn * 64 + ni * 8 + g;                                                  \
            bfr[ni][0] = *reinterpret_cast<const unsigned*>(&sB[n][kk + 2 * t]);           \
            bfr[ni][1] = *reinterpret_cast<const unsigned*>(&sB[n][kk + 8 + 2 * t]);       \
        }                                                                                  \
        _Pragma("unroll")                                                                  \
        for (int mi = 0; mi < 2; mi++)                                                     \
            _Pragma("unroll")                                                              \
            for (int ni = 0; ni < 8; ni++) mma_bf16(acc[mi][ni], af[mi], bfr[ni]);         \
    }

__global__ __launch_bounds__(256) void softmax_sum_kernel(const float* __restrict__ base_rates) {
    SOFTMAX_TILE_PROLOGUE

    float ps[2][2] = {{0.f, 0.f}, {0.f, 0.f}};
#pragma unroll
    for (int mi = 0; mi < 2; mi++)
#pragma unroll
        for (int ni = 0; ni < 8; ni++) {
            int v = v0 + wn * 64 + ni * 8 + 2 * t;
            if (v < VDIM) {
                float br0 = base_rates[v], br1 = base_rates[v + 1];
                ps[mi][0] += __expf(acc[mi][ni][0] + br0) + __expf(acc[mi][ni][1] + br1);
                ps[mi][1] += __expf(acc[mi][ni][2] + br0) + __expf(acc[mi][ni][3] + br1);
            }
        }
#pragma unroll
    for (int mi = 0; mi < 2; mi++)
#pragma unroll
        for (int hh = 0; hh < 2; hh++) {
            float v = ps[mi][hh];
            v += __shfl_xor_sync(0xffffffffu, v, 1);
            v += __shfl_xor_sync(0xffffffffu, v, 2);
            if (t == 0) atomicAdd(&s_sum[wm * 32 + mi * 16 + g + hh * 8], v);
        }
    __syncthreads();
    if (tid < 128) atomicAdd(&g_sumexp[m0 + tid], s_sum[tid]);
}

__global__ __launch_bounds__(256) void recon_kernel(const float* __restrict__ base_rates,
                                                    const float* __restrict__ bows) {
    SOFTMAX_TILE_PROLOGUE

    float ps[2][2] = {{0.f, 0.f}, {0.f, 0.f}};
    float cS[2][2], lS[2][2];
#pragma unroll
    for (int mi = 0; mi < 2; mi++)
#pragma unroll
        for (int hh = 0; hh < 2; hh++) {
            float s = g_sumexp[m0 + wm * 32 + mi * 16 + g + hh * 8];
            cS[mi][hh] = 1e-6f * s;
            lS[mi][hh] = __logf(s);
        }
#pragma unroll
    for (int mi = 0; mi < 2; mi++)
#pragma unroll
        for (int ni = 0; ni < 8; ni++) {
            int v = v0 + wn * 64 + ni * 8 + 2 * t;
            if (v < VDIM) {
                float br0 = base_rates[v], br1 = base_rates[v + 1];
                int r1 = m0 + wm * 32 + mi * 16 + g;
                float2 bw1 = *reinterpret_cast<const float2*>(bows + (size_t)r1 * VDIM + v);
                float2 bw2 = *reinterpret_cast<const float2*>(bows + (size_t)(r1 + 8) * VDIM + v);
                ps[mi][0] += (__logf(__expf(acc[mi][ni][0] + br0) + cS[mi][0]) - lS[mi][0]) * bw1.x
                           + (__logf(__expf(acc[mi][ni][1] + br1) + cS[mi][0]) - lS[mi][0]) * bw1.y;
                ps[mi][1] += (__logf(__expf(acc[mi][ni][2] + br0) + cS[mi][1]) - lS[mi][1]) * bw2.x
                           + (__logf(__expf(acc[mi][ni][3] + br1) + cS[mi][1]) - lS[mi][1]) * bw2.y;
            }
        }
#pragma unroll
    for (int mi = 0; mi < 2; mi++)
#pragma unroll
        for (int hh = 0; hh < 2; hh++) {
            float v = ps[mi][hh];
            v += __shfl_xor_sync(0xffffffffu, v, 1);
            v += __shfl_xor_sync(0xffffffffu, v, 2);
            if (t == 0) atomicAdd(&s_sum[wm * 32 + mi * 16 + g + hh * 8], v);
        }
    __syncthreads();
    if (tid < 128) atomicAdd(&g_reconrow[m0 + tid], s_sum[tid]);
}

// ---------------- final deterministic reduction ----------------
__device__ float block_sum256(float x, float* red) {
    int tid = threadIdx.x;
    red[tid] = x;
    __syncthreads();
    for (int off = 128; off; off >>= 1) {
        if (tid < off) red[tid] += red[tid + off];
        __syncthreads();
    }
    float r = red[0];
    __syncthreads();
    return r;
}

__global__ void final_kernel(const float* __restrict__ labels, const float* __restrict__ base_rates,
                             const float* __restrict__ bow_w, const float* __restrict__ topic_w,
                             const float* __restrict__ bow_b, const float* __restrict__ topic_b,
                             float* __restrict__ out, int n_gamma_parts) {
    __shared__ float red[256];
    int tid = threadIdx.x;
    float sumRecon = 0.f, sumKld = 0.f, sumMse = 0.f, sumBase = 0.f, sumBw2 = 0.f, sumGam = 0.f;
    for (int b = tid; b < BDIM; b += 256) {
        sumRecon += g_reconrow[b];
        sumKld += g_kldrow[b];
        float pred = bow_b[0] + topic_b[0] + g_P[b * 64 + 50];
        for (int k = 0; k < KDIM; k++) {
            float th = g_theta[b * KDIM + k];
            pred += th * (g_P[b * 64 + k] + topic_w[k]);
        }
        float d = pred - labels[b];
        sumMse += d * d;
    }
    for (int v = tid; v < VDIM; v += 256) {
        sumBase += fabsf(base_rates[v]);
        float w = bow_w[v];
        sumBw2 += w * w;
    }
    for (int i = tid; i < n_gamma_parts; i += 256) sumGam += g_gammapart[i];

    float sr = block_sum256(sumRecon, red);
    float sk = block_sum256(sumKld, red);
    float sm = block_sum256(sumMse, red);
    float sb = block_sum256(sumBase, red);
    float sw2 = block_sum256(sumBw2, red);
    float sg = block_sum256(sumGam, red);
    if (tid == 0) {
        out[0] = -sr / (float)BDIM;
        out[1] = 0.0005f * sb + sm / (float)BDIM + 0.000005f * sg + 0.0005f * sqrtf(sw2);
        out[2] = -0.5f * sk / (float)BDIM;
    }
}

// ---------------- launch ----------------
extern "C" void kernel_launch(void* const* d_in, const int* in_sizes, int n_in,
                              void* d_out, int out_size) {
    const float* bows    = (const float*)d_in[0];
    const float* nb      = (const float*)d_in[1];
    const float* labels  = (const float*)d_in[2];
    const float* W1      = (const float*)d_in[3];
    const float* b1      = (const float*)d_in[4];
    const float* W2      = (const float*)d_in[5];
    const float* b2      = (const float*)d_in[6];
    const float* bn1g    = (const float*)d_in[7];
    const float* bn1b    = (const float*)d_in[8];
    const float* bn1m    = (const float*)d_in[9];
    const float* bn1v    = (const float*)d_in[10];
    const float* bn2g    = (const float*)d_in[11];
    const float* bn2b    = (const float*)d_in[12];
    const float* bn2m    = (const float*)d_in[13];
    const float* bn2v    = (const float*)d_in[14];
    const float* muW     = (const float*)d_in[15];
    const float* mub     = (const float*)d_in[16];
    const float* lsW     = (const float*)d_in[17];
    const float* lsb     = (const float*)d_in[18];
    const float* beta    = (const float*)d_in[19];
    const float* gam     = (const float*)d_in[20];
    const float* base    = (const float*)d_in[21];
    const float* bow_w   = (const float*)d_in[22];
    const float* bow_b   = (const float*)d_in[23];
    const float* topic_w = (const float*)d_in[24];
    const float* topic_b = (const float*)d_in[25];
    float* out = (float*)d_out;

    const int nGammaBlocks = (VDIM + 63) / 64;  // 782
    const int nVBlocks = (VDIM + 127) / 128;    // 391

    // attribute set only (no allocation) — needed for 61.4KB dynamic smem
    cudaFuncSetAttribute(gemm_big_kernel,
                         cudaFuncAttributeMaxDynamicSharedMemorySize, GB_SMEM_BYTES);

    prep_kernel<<<nGammaBlocks, 256>>>(beta, gam, bow_w, muW, lsW);
    gemm_big_kernel<<<dim3(BDIM / BM, (NTOT + BNT - 1) / BNT, 24), 256, GB_SMEM_BYTES>>>(nb, W1);
    stage2_mma_kernel<<<dim3(BDIM / S2BM, (HDIM + S2BNT - 1) / S2BNT), 256>>>(
        b1, bn1g, bn1b, bn1m, bn1v, W2, b2, bn2g, bn2b, bn2m, bn2v);
    stage3_kernel<<<BDIM, 64>>>(mub, lsb);
    softmax_sum_kernel<<<dim3(BDIM / 128, nVBlocks), 256>>>(base);
    recon_kernel<<<dim3(BDIM / 128, nVBlocks), 256>>>(base, bows);
    final_kernel<<<1, 256>>>(labels, base, bow_w, topic_w, bow_b, topic_b, out, nGammaBlocks);
}

// round 16
// speedup vs baseline: 1.2605x; 1.0729x over previous
#include <cuda_runtime.h>
#include <cuda_bf16.h>
#include <cstdint>

// ---------------- problem constants ----------------
#define VDIM 50000
#define VPAD 50048          // 782*64, padded for bf16 beta array
#define KDIM 50
#define HDIM 300
#define BDIM 512
#define NTOT 351            // 300 (W1 cols) + 51 (sbeta/bow_w cols)
#define BN_EPS 1e-5f
#define S2_KPAD 320         // padded K for stage2/stage3 MMA

// ---------------- scratch (device globals; no allocs allowed) ----------------
__device__ float         g_hpre[BDIM * HDIM];           // 512x300
__device__ float         g_P[BDIM * 64];                // cols 0..49 = nb@sbeta, col 50 = nb@bow_w
__device__ float         g_h2[BDIM * HDIM];
__device__ float         g_muls[BDIM * 128];            // cols 0..49 = mu (raw), 50..99 = logsigma (raw)
__device__ float         g_theta[BDIM * KDIM];
__device__ __nv_bfloat16 g_thetab16[BDIM * 64];         // zero-padded to K=64
__device__ float         g_kldrow[BDIM];
__device__ float         g_sumexp[BDIM];                // per-row sum of exp(logits)
__device__ float         g_reconrow[BDIM];              // per-row recon sum (atomic accum)
__device__ float         g_gammapart[800];
__device__ float         g_sbetaT[51 * VDIM];           // rows 0..49: (beta*gamma)^T, row 50: bow_w
__device__ __nv_bfloat16 g_betab16[(size_t)VPAD * 64];  // beta rows as bf16, zero-padded

// ---------------- mma helper ----------------
__device__ __forceinline__ void mma_bf16(float* d, const unsigned* a, const unsigned* b) {
    asm volatile(
        "mma.sync.aligned.m16n8k16.row.col.f32.bf16.bf16.f32 "
        "{%0,%1,%2,%3}, {%4,%5,%6,%7}, {%8,%9}, {%0,%1,%2,%3};\n"
        : "+f"(d[0]), "+f"(d[1]), "+f"(d[2]), "+f"(d[3])
        : "r"(a[0]), "r"(a[1]), "r"(a[2]), "r"(a[3]), "r"(b[0]), "r"(b[1]));
}

__device__ __forceinline__ void split_hl(float x, __nv_bfloat16& h, __nv_bfloat16& l) {
    h = __float2bfloat16(x);
    l = __float2bfloat16(x - __bfloat162float(h));
}

// ---------------- prep: zeroing, sbetaT, bf16 beta, Sum|gamma| partials ----
__global__ __launch_bounds__(256) void prep_kernel(const float* __restrict__ beta,
                                                   const float* __restrict__ gam,
                                                   const float* __restrict__ bow_w) {
    __shared__ float tile[64][51];
    __shared__ float rs[256];
    int v0 = blockIdx.x * 64;
    int tid = threadIdx.x;

    // grid-stride zeroing (782 blocks x 256 = 200192 threads)
    int gtid = blockIdx.x * 256 + tid;
    if (gtid < BDIM * HDIM) g_hpre[gtid] = 0.f;
    if (gtid < BDIM * 64)   g_P[gtid] = 0.f;
    if (gtid < BDIM) { g_sumexp[gtid] = 0.f; g_reconrow[gtid] = 0.f; }

    float asum = 0.f;
    for (int idx = tid; idx < 64 * KDIM; idx += 256) {
        int r = idx / KDIM, c = idx % KDIM;
        int v = v0 + r;
        float s = 0.f;
        if (v < VDIM) {
            float bb = beta[(size_t)v * KDIM + c];
            float gg = gam[(size_t)v * KDIM + c];
            s = bb * gg;
            asum += fabsf(gg);
        }
        tile[r][c] = s;
    }
    // bf16 beta copy, zero-padded to [VPAD][64]
    for (int idx = tid; idx < 64 * 64; idx += 256) {
        int r = idx >> 6, c = idx & 63;
        int v = v0 + r;
        float val = (c < KDIM && v < VDIM) ? beta[(size_t)v * KDIM + c] : 0.f;
        g_betab16[(size_t)(v0 + r) * 64 + c] = __float2bfloat16(val);
    }
    __syncthreads();
    for (int idx = tid; idx < KDIM * 64; idx += 256) {
        int k = idx >> 6, j = idx & 63;
        int v = v0 + j;
        if (v < VDIM) g_sbetaT[(size_t)k * VDIM + v] = tile[j][k];
    }
    for (int j = tid; j < 64; j += 256) {
        int v = v0 + j;
        if (v < VDIM) g_sbetaT[(size_t)50 * VDIM + v] = bow_w[v];
    }
    rs[tid] = asum;
    __syncthreads();
    for (int off = 128; off; off >>= 1) {
        if (tid < off) rs[tid] += rs[tid + off];
        __syncthreads();
    }
    if (tid == 0) g_gammapart[blockIdx.x] = rs[0];
}

// =====================================================================
// Fused big GEMM: [hpre | P] = nb @ [W1 | sbetaT]^T      (R11 champion)
// =====================================================================
#define BM 128
#define BNT 128
#define BK 32
#define SPLIT_LEN 2112          // 66 * 32 ; 24 splits cover 50688 >= 50000
#define NSTAGES (SPLIT_LEN / BK)
#define GB_SEG (2 * 128 * 40)   // bf16 elements per operand buffer
#define GB_SMEM_BYTES (3 * GB_SEG * 2)

__global__ __launch_bounds__(256) void gemm_big_kernel(const float* __restrict__ A,
                                                       const float* __restrict__ W1) {
    extern __shared__ __nv_bfloat16 dsm[];
#define SA_(buf,r,k)  dsm[((buf) * 128 + (r)) * 40 + (k)]
#define SBH_(buf,r,k) dsm[GB_SEG + ((buf) * 128 + (r)) * 40 + (k)]
#define SBL_(buf,r,k) dsm[2 * GB_SEG + ((buf) * 128 + (r)) * 40 + (k)]

    const int tid = threadIdx.x;
    const int m0 = blockIdx.x * BM;
    const int n0 = blockIdx.y * BNT;
    const int kstart = blockIdx.z * SPLIT_LEN;

    const int warpId = tid >> 5, lane = tid & 31;
    const int wm = warpId >> 1, wn = warpId & 1;
    const int g = lane >> 2, t = lane & 3;

    float acc[2][2][4][4];
#pragma unroll
    for (int hf = 0; hf < 2; hf++)
#pragma unroll
        for (int mi = 0; mi < 2; mi++)
#pragma unroll
            for (int ni = 0; ni < 4; ni++)
#pragma unroll
                for (int e = 0; e < 4; e++) acc[hf][mi][ni][e] = 0.f;

    float4 ra[4], rb[4];

    auto ldA = [&](int stage) {
        int kb = kstart + stage * BK;
#pragma unroll
        for (int q = 0; q < 4; q++) {
            int qi = tid + q * 256;
            int r = qi >> 3;
            int k = kb + (qi & 7) * 4;
            float4 v = make_float4(0.f, 0.f, 0.f, 0.f);
            if (k < VDIM) v = *reinterpret_cast<const float4*>(A + (size_t)(m0 + r) * VDIM + k);
            ra[q] = v;
        }
    };
    auto ldB = [&](int stage) {
        int kb = kstart + stage * BK;
#pragma unroll
        for (int q = 0; q < 4; q++) {
            int qi = tid + q * 256;
            int r = qi >> 3;
            int k = kb + (qi & 7) * 4;
            int n = n0 + r;
            float4 v = make_float4(0.f, 0.f, 0.f, 0.f);
            if (k < VDIM && n < NTOT) {
                const float* src = (n < HDIM) ? (W1 + (size_t)n * VDIM)
                                              : (g_sbetaT + (size_t)(n - HDIM) * VDIM);
                v = *reinterpret_cast<const float4*>(src + k);
            }
            rb[q] = v;
        }
    };
    auto stAB = [&](int buf) {
#pragma unroll
        for (int q = 0; q < 4; q++) {
            int qi = tid + q * 256;
            int r = qi >> 3;
            int kq = (qi & 7) * 4;
            SA_(buf, r, kq)     = __float2bfloat16(ra[q].x);
            SA_(buf, r, kq + 1) = __float2bfloat16(ra[q].y);
            SA_(buf, r, kq + 2) = __float2bfloat16(ra[q].z);
            SA_(buf, r, kq + 3) = __float2bfloat16(ra[q].w);
        }
#pragma unroll
        for (int q = 0; q < 4; q++) {
            int qi = tid + q * 256;
            int r = qi >> 3;
            int kq = (qi & 7) * 4;
            const float* pv = &rb[q].x;
#pragma unroll
            for (int e = 0; e < 4; e++) {
                __nv_bfloat16 h, l;
                split_hl(pv[e], h, l);
                SBH_(buf, r, kq + e) = h;
                SBL_(buf, r, kq + e) = l;
            }
        }
    };
    auto compute = [&](int buf) {
#pragma unroll
        for (int kk = 0; kk < BK; kk += 16) {
            unsigned af[2][4];
#pragma unroll
            for (int mi = 0; mi < 2; mi++) {
                int r = wm * 32 + mi * 16 + g;
                af[mi][0] = *reinterpret_cast<const unsigned*>(&SA_(buf, r, kk + 2 * t));
                af[mi][1] = *reinterpret_cast<const unsigned*>(&SA_(buf, r + 8, kk + 2 * t));
                af[mi][2] = *reinterpret_cast<const unsigned*>(&SA_(buf, r, kk + 8 + 2 * t));
                af[mi][3] = *reinterpret_cast<const unsigned*>(&SA_(buf, r + 8, kk + 8 + 2 * t));
            }
#pragma unroll
            for (int hf = 0; hf < 2; hf++) {
                unsigned bh[4][2], bl[4][2];
#pragma unroll
                for (int ni = 0; ni < 4; ni++) {
                    int n = hf * 64 + wn * 32 + ni * 8 + g;
                    bh[ni][0] = *reinterpret_cast<const unsigned*>(&SBH_(buf, n, kk + 2 * t));
                    bh[ni][1] = *reinterpret_cast<const unsigned*>(&SBH_(buf, n, kk + 8 + 2 * t));
                    bl[ni][0] = *reinterpret_cast<const unsigned*>(&SBL_(buf, n, kk + 2 * t));
                    bl[ni][1] = *reinterpret_cast<const unsigned*>(&SBL_(buf, n, kk + 8 + 2 * t));
                }
#pragma unroll
                for (int mi = 0; mi < 2; mi++)
#pragma unroll
                    for (int ni = 0; ni < 4; ni++) {
                        mma_bf16(acc[hf][mi][ni], af[mi], bh[ni]);
                        mma_bf16(acc[hf][mi][ni], af[mi], bl[ni]);
                    }
            }
        }
    };

    ldA(0); ldB(0);
    stAB(0);
    __syncthreads();
    for (int s = 0; s < NSTAGES; s++) {
        int cur = s & 1;
        if (s + 1 < NSTAGES) { ldA(s + 1); ldB(s + 1); }
        compute(cur);
        if (s + 1 < NSTAGES) {
            __syncthreads();
            stAB(cur ^ 1);
            __syncthreads();
        }
    }

#pragma unroll
    for (int hf = 0; hf < 2; hf++)
#pragma unroll
        for (int mi = 0; mi < 2; mi++)
#pragma unroll
            for (int ni = 0; ni < 4; ni++)
#pragma unroll
                for (int e = 0; e < 4; e++) {
                    int row = m0 + wm * 32 + mi * 16 + g + ((e >= 2) ? 8 : 0);
                    int col = n0 + hf * 64 + wn * 32 + ni * 8 + 2 * t + (e & 1);
                    float v = acc[hf][mi][ni][e];
                    if (col < HDIM) atomicAdd(&g_hpre[row * HDIM + col], v);
                    else if (col < NTOT) atomicAdd(&g_P[row * 64 + (col - HDIM)], v);
                }
#undef SA_
#undef SBH_
#undef SBL_
}

// =====================================================================
// stage2 (bn1 fused): h2 = bn2(relu( bn1(relu(hpre+b1)) @ W2^T + b2 ))
// BM=64, BNT=32, grid (8,10)=80 blocks, 8 warps as 2(m) x 4(n).
// =====================================================================
#define S2BM 64
#define S2BNT 32
#define S2_NSTAGES (S2_KPAD / BK)   // 10

__global__ __launch_bounds__(256) void stage2_mma_kernel(
    const float* __restrict__ b1_, const float* __restrict__ bn1g,
    const float* __restrict__ bn1b, const float* __restrict__ bn1m,
    const float* __restrict__ bn1v,
    const float* __restrict__ W2, const float* __restrict__ b2,
    const float* __restrict__ bn2g, const float* __restrict__ bn2b,
    const float* __restrict__ bn2m, const float* __restrict__ bn2v) {
    __shared__ __nv_bfloat16 sA[2][S2BM][BK + 8];
    __shared__ __nv_bfloat16 sBh[2][S2BNT][BK + 8];
    __shared__ __nv_bfloat16 sBl[2][S2BNT][BK + 8];
    __shared__ float sb1[S2_KPAD], sA1[S2_KPAD], sA0[S2_KPAD];

    const int tid = threadIdx.x;
    const int m0 = blockIdx.x * S2BM;
    const int n0 = blockIdx.y * S2BNT;

    const int warpId = tid >> 5, lane = tid & 31;
    const int wm2 = warpId >> 2, wn2 = warpId & 3;
    const int g = lane >> 2, t = lane & 3;

    for (int c = tid; c < S2_KPAD; c += 256) {
        float s = 0.f, a0 = 0.f, bb = 0.f;
        if (c < HDIM) {
            s = rsqrtf(bn1v[c] + BN_EPS) * bn1g[c];
            a0 = bn1b[c] - bn1m[c] * s;
            bb = b1_[c];
        }
        sb1[c] = bb; sA1[c] = s; sA0[c] = a0;
    }
    __syncthreads();

    float acc[2][4];
#pragma unroll
    for (int mi = 0; mi < 2; mi++)
#pragma unroll
        for (int e = 0; e < 4; e++) acc[mi][e] = 0.f;

    float4 ra[2], rb;

    auto ldA = [&](int stage) {
        int kb = stage * BK;
#pragma unroll
        for (int q = 0; q < 2; q++) {
            int qi = tid + q * 256;
            int r = qi >> 3;
            int kq = (qi & 7) * 4;
            int k = kb + kq;
            float4 v = make_float4(0.f, 0.f, 0.f, 0.f);
            if (k < HDIM) v = *reinterpret_cast<const float4*>(g_hpre + (m0 + r) * HDIM + k);
            float* pv = &v.x;
#pragma unroll
            for (int e = 0; e < 4; e++) {
                float val = fmaxf(pv[e] + sb1[k + e], 0.f);
                pv[e] = val * sA1[k + e] + sA0[k + e];
            }
            ra[q] = v;
        }
    };
    auto ldB = [&](int stage) {
        int kb = stage * BK;
        int r = tid >> 3;
        int kq = (tid & 7) * 4;
        int k = kb + kq;
        int n = n0 + r;
        float4 v = make_float4(0.f, 0.f, 0.f, 0.f);
        if (k < HDIM && n < HDIM) v = *reinterpret_cast<const float4*>(W2 + (size_t)n * HDIM + k);
        rb = v;
    };
    auto stAB = [&](int buf) {
#pragma unroll
        for (int q = 0; q < 2; q++) {
            int qi = tid + q * 256;
            int r = qi >> 3;
            int kq = (qi & 7) * 4;
            sA[buf][r][kq]     = __float2bfloat16(ra[q].x);
            sA[buf][r][kq + 1] = __float2bfloat16(ra[q].y);
            sA[buf][r][kq + 2] = __float2bfloat16(ra[q].z);
            sA[buf][r][kq + 3] = __float2bfloat16(ra[q].w);
        }
        {
            int r = tid >> 3;
            int kq = (tid & 7) * 4;
            const float* pv = &rb.x;
#pragma unroll
            for (int e = 0; e < 4; e++) {
                __nv_bfloat16 h, l;
                split_hl(pv[e], h, l);
                sBh[buf][r][kq + e] = h;
                sBl[buf][r][kq + e] = l;
            }
        }
    };
    auto compute = [&](int buf) {
#pragma unroll
        for (int kk = 0; kk < BK; kk += 16) {
            unsigned af[2][4], bh[2], bl[2];
#pragma unroll
            for (int mi = 0; mi < 2; mi++) {
                int r = wm2 * 32 + mi * 16 + g;
                af[mi][0] = *reinterpret_cast<const unsigned*>(&sA[buf][r][kk + 2 * t]);
                af[mi][1] = *reinterpret_cast<const unsigned*>(&sA[buf][r + 8][kk + 2 * t]);
                af[mi][2] = *reinterpret_cast<const unsigned*>(&sA[buf][r][kk + 8 + 2 * t]);
                af[mi][3] = *reinterpret_cast<const unsigned*>(&sA[buf][r + 8][kk + 8 + 2 * t]);
            }
            {
                int n = wn2 * 8 + g;
                bh[0] = *reinterpret_cast<const unsigned*>(&sBh[buf][n][kk + 2 * t]);
                bh[1] = *reinterpret_cast<const unsigned*>(&sBh[buf][n][kk + 8 + 2 * t]);
                bl[0] = *reinterpret_cast<const unsigned*>(&sBl[buf][n][kk + 2 * t]);
                bl[1] = *reinterpret_cast<const unsigned*>(&sBl[buf][n][kk + 8 + 2 * t]);
            }
#pragma unroll
            for (int mi = 0; mi < 2; mi++) {
                mma_bf16(acc[mi], af[mi], bh);
                mma_bf16(acc[mi], af[mi], bl);
            }
        }
    };

    ldA(0); ldB(0);
    stAB(0);
    __syncthreads();
    for (int s = 0; s < S2_NSTAGES; s++) {
        int cur = s & 1;
        if (s + 1 < S2_NSTAGES) { ldA(s + 1); ldB(s + 1); }
        compute(cur);
        if (s + 1 < S2_NSTAGES) {
            __syncthreads();
            stAB(cur ^ 1);
            __syncthreads();
        }
    }

#pragma unroll
    for (int mi = 0; mi < 2; mi++)
#pragma unroll
        for (int e = 0; e < 4; e++) {
            int row = m0 + wm2 * 32 + mi * 16 + g + ((e >= 2) ? 8 : 0);
            int col = n0 + wn2 * 8 + 2 * t + (e & 1);
            if (col < HDIM) {
                float x = fmaxf(acc[mi][e] + b2[col], 0.f);
                x = (x - bn2m[col]) * rsqrtf(bn2v[col] + BN_EPS) * bn2g[col] + bn2b[col];
                g_h2[row * HDIM + col] = x;
            }
        }
}

// =====================================================================
// stage3 MMA: [mu | ls](raw) = h2 @ [muW ; lsW]^T   (N=100)
// Same proven tiling as stage2: BM=64, BNT=32, grid (8,4)=32 blocks.
// A = g_h2 f32 -> bf16 in-register; B hi/lo split.
// =====================================================================
__global__ __launch_bounds__(256) void stage3_mma_kernel(const float* __restrict__ muW,
                                                         const float* __restrict__ lsW) {
    __shared__ __nv_bfloat16 sA[2][S2BM][BK + 8];
    __shared__ __nv_bfloat16 sBh[2][S2BNT][BK + 8];
    __shared__ __nv_bfloat16 sBl[2][S2BNT][BK + 8];

    const int tid = threadIdx.x;
    const int m0 = blockIdx.x * S2BM;
    const int n0 = blockIdx.y * S2BNT;

    const int warpId = tid >> 5, lane = tid & 31;
    const int wm2 = warpId >> 2, wn2 = warpId & 3;
    const int g = lane >> 2, t = lane & 3;

    float acc[2][4];
#pragma unroll
    for (int mi = 0; mi < 2; mi++)
#pragma unroll
        for (int e = 0; e < 4; e++) acc[mi][e] = 0.f;

    float4 ra[2], rb;

    auto ldA = [&](int stage) {
        int kb = stage * BK;
#pragma unroll
        for (int q = 0; q < 2; q++) {
            int qi = tid + q * 256;
            int r = qi >> 3;
            int kq = (qi & 7) * 4;
            int k = kb + kq;
            float4 v = make_float4(0.f, 0.f, 0.f, 0.f);
            if (k < HDIM) v = *reinterpret_cast<const float4*>(g_h2 + (m0 + r) * HDIM + k);
            ra[q] = v;
        }
    };
    auto ldB = [&](int stage) {
        int kb = stage * BK;
        int r = tid >> 3;
        int kq = (tid & 7) * 4;
        int k = kb + kq;
        int n = n0 + r;
        float4 v = make_float4(0.f, 0.f, 0.f, 0.f);
        if (k < HDIM && n < 2 * KDIM) {
            const float* src = (n < KDIM) ? (muW + (size_t)n * HDIM)
                                          : (lsW + (size_t)(n - KDIM) * HDIM);
            v = *reinterpret_cast<const float4*>(src + k);
        }
        rb = v;
    };
    auto stAB = [&](int buf) {
#pragma unroll
        for (int q = 0; q < 2; q++) {
            int qi = tid + q * 256;
            int r = qi >> 3;
            int kq = (qi & 7) * 4;
            sA[buf][r][kq]     = __float2bfloat16(ra[q].x);
            sA[buf][r][kq + 1] = __float2bfloat16(ra[q].y);
            sA[buf][r][kq + 2] = __float2bfloat16(ra[q].z);
            sA[buf][r][kq + 3] = __float2bfloat16(ra[q].w);
        }
        {
            int r = tid >> 3;
            int kq = (tid & 7) * 4;
            const float* pv = &rb.x;
#pragma unroll
            for (int e = 0; e < 4; e++) {
                __nv_bfloat16 h, l;
                split_hl(pv[e], h, l);
                sBh[buf][r][kq + e] = h;
                sBl[buf][r][kq + e] = l;
            }
        }
    };
    auto compute = [&](int buf) {
#pragma unroll
        for (int kk = 0; kk < BK; kk += 16) {
            unsigned af[2][4], bh[2], bl[2];
#pragma unroll
            for (int mi = 0; mi < 2; mi++) {
                int r = wm2 * 32 + mi * 16 + g;
                af[mi][0] = *reinterpret_cast<const unsigned*>(&sA[buf][r][kk + 2 * t]);
                af[mi][1] = *reinterpret_cast<const unsigned*>(&sA[buf][r + 8][kk + 2 * t]);
                af[mi][2] = *reinterpret_cast<const unsigned*>(&sA[buf][r][kk + 8 + 2 * t]);
                af[mi][3] = *reinterpret_cast<const unsigned*>(&sA[buf][r + 8][kk + 8 + 2 * t]);
            }
            {
                int n = wn2 * 8 + g;
                bh[0] = *reinterpret_cast<const unsigned*>(&sBh[buf][n][kk + 2 * t]);
                bh[1] = *reinterpret_cast<const unsigned*>(&sBh[buf][n][kk + 8 + 2 * t]);
                bl[0] = *reinterpret_cast<const unsigned*>(&sBl[buf][n][kk + 2 * t]);
                bl[1] = *reinterpret_cast<const unsigned*>(&sBl[buf][n][kk + 8 + 2 * t]);
            }
#pragma unroll
            for (int mi = 0; mi < 2; mi++) {
                mma_bf16(acc[mi], af[mi], bh);
                mma_bf16(acc[mi], af[mi], bl);
            }
        }
    };

    ldA(0); ldB(0);
    stAB(0);
    __syncthreads();
    for (int s = 0; s < S2_NSTAGES; s++) {
        int cur = s & 1;
        if (s + 1 < S2_NSTAGES) { ldA(s + 1); ldB(s + 1); }
        compute(cur);
        if (s + 1 < S2_NSTAGES) {
            __syncthreads();
            stAB(cur ^ 1);
            __syncthreads();
        }
    }

#pragma unroll
    for (int mi = 0; mi < 2; mi++)
#pragma unroll
        for (int e = 0; e < 4; e++) {
            int row = m0 + wm2 * 32 + mi * 16 + g + ((e >= 2) ? 8 : 0);
            int col = n0 + wn2 * 8 + 2 * t + (e & 1);
            if (col < 2 * KDIM) g_muls[row * 128 + col] = acc[mi][e];
        }
}

// ---------------- stage3 finish: bias + softmax + theta + kld ----------------
__global__ void stage3_fin_kernel(const float* __restrict__ mub, const float* __restrict__ lsb) {
    int b = blockIdx.x;
    int tid = threadIdx.x;   // 64 threads
    __shared__ float mus[KDIM];
    __shared__ float klds[64];
    __shared__ float red2[2];
    float kld_part = 0.f;
    if (tid < KDIM) {
        float mu = g_muls[b * 128 + tid] + mub[tid];
        float ls = g_muls[b * 128 + KDIM + tid] + lsb[tid];
        mus[tid] = mu;
        kld_part = 1.f + ls - mu * mu - __expf(ls);
    }
    klds[tid] = (tid < KDIM) ? kld_part : 0.f;
    __syncthreads();
    if (tid == 0) {
        float mx = -1e30f;
        for (int k = 0; k < KDIM; k++) mx = fmaxf(mx, mus[k]);
        float s = 0.f;
        for (int k = 0; k < KDIM; k++) s += __expf(mus[k] - mx);
        red2[0] = mx; red2[1] = s;
        float kk = 0.f;
        for (int k = 0; k < KDIM; k++) kk += klds[k];
        g_kldrow[b] = kk;
    }
    __syncthreads();
    if (tid < KDIM) {
        float th = __expf(mus[tid] - red2[0]) / red2[1];
        g_theta[b * KDIM + tid] = th;
        g_thetab16[b * 64 + tid] = __float2bfloat16(th);
    } else {
        g_thetab16[b * 64 + tid] = __float2bfloat16(0.f);
    }
}

// =====================================================================
// Softmax passes: recompute logits tiles; sB from precomputed bf16 beta.
// =====================================================================
#define SOFTMAX_TILE_PROLOGUE                                                              \
    __shared__ __nv_bfloat16 sA[128][72];                                                  \
    __shared__ __nv_bfloat16 sB[128][72];                                                  \
    __shared__ float s_sum[128];                                                           \
    int tid = threadIdx.x;                                                                 \
    int m0 = blockIdx.x * 128, v0 = blockIdx.y * 128;                                      \
    for (int i = tid; i < 128; i += 256) s_sum[i] = 0.f;                                   \
    _Pragma("unroll")                                                                      \
    for (int q = 0; q < 4; q++) {                                                          \
        int qi = tid + q * 256;                                                            \
        int r = qi >> 3;                                                                   \
        int c8 = (qi & 7) * 8;                                                             \
        uint4 u = *reinterpret_cast<const uint4*>(&g_thetab16[(m0 + r) * 64 + c8]);        \
        *reinterpret_cast<uint4*>(&sA[r][c8]) = u;                                         \
        uint4 ub = *reinterpret_cast<const uint4*>(&g_betab16[(size_t)(v0 + r) * 64 + c8]);\
        *reinterpret_cast<uint4*>(&sB[r][c8]) = ub;                                        \
    }                                                                                      \
    __syncthreads();                                                                       \
    const int warpId = tid >> 5, lane = tid & 31;                                          \
    const int wm = warpId >> 1, wn = warpId & 1;                                           \
    const int g = lane >> 2, t = lane & 3;                                                 \
    float acc[2][8][4];                                                                    \
    _Pragma("unroll")                                                                      \
    for (int mi = 0; mi < 2; mi++)                                                         \
        _Pragma("unroll")                                                                  \
        for (int ni = 0; ni < 8; ni++)                                                     \
            _Pragma("unroll")                                                              \
            for (int e = 0; e < 4; e++) acc[mi][ni][e] = 0.f;                              \
    _Pragma("unroll")                                                                      \
    for (int kk = 0; kk < 64; kk += 16) {                                                  \
        unsigned af[2][4], bfr[8][2];                                                      \
        _Pragma("unroll")                                                                  \
        for (int mi = 0; mi < 2; mi++) {                                                   \
            int r = wm * 32 + mi * 16 + g;                                                 \
            af[mi][0] = *reinterpret_cast<const unsigned*>(&sA[r][kk + 2 * t]);            \
            af[mi][1] = *reinterpret_cast<const unsigned*>(&sA[r + 8][kk + 2 * t]);        \
            af[mi][2] = *reinterpret_cast<const unsigned*>(&sA[r][kk + 8 + 2 * t]);        \
            af[mi][3] = *reinterpret_cast<const unsigned*>(&sA[r + 8][kk + 8 + 2 * t]);    \
        }                                                                                  \
        _Pragma("unroll")                                                                  \
        for (int ni = 0; ni < 8; ni++) {                                                   \
            int n = wn * 64 + ni * 8 + g;                                                  \
            bfr[ni][0] = *reinterpret_cast<const unsigned*>(&sB[n][kk + 2 * t]);           \
            bfr[ni][1] = *reinterpret_cast<const unsigned*>(&sB[n][kk + 8 + 2 * t]);       \
        }                                                                                  \
        _Pragma("unroll")                                                                  \
        for (int mi = 0; mi < 2; mi++)                                                     \
            _Pragma("unroll")                                                              \
            for (int ni = 0; ni < 8; ni++) mma_bf16(acc[mi][ni], af[mi], bfr[ni]);         \
    }

__global__ __launch_bounds__(256) void softmax_sum_kernel(const float* __restrict__ base_rates) {
    SOFTMAX_TILE_PROLOGUE

    float ps[2][2] = {{0.f, 0.f}, {0.f, 0.f}};
#pragma unroll
    for (int mi = 0; mi < 2; mi++)
#pragma unroll
        for (int ni = 0; ni < 8; ni++) {
            int v = v0 + wn * 64 + ni * 8 + 2 * t;
            if (v < VDIM) {
                float br0 = base_rates[v], br1 = base_rates[v + 1];
                ps[mi][0] += __expf(acc[mi][ni][0] + br0) + __expf(acc[mi][ni][1] + br1);
                ps[mi][1] += __expf(acc[mi][ni][2] + br0) + __expf(acc[mi][ni][3] + br1);
            }
        }
#pragma unroll
    for (int mi = 0; mi < 2; mi++)
#pragma unroll
        for (int hh = 0; hh < 2; hh++) {
            float v = ps[mi][hh];
            v += __shfl_xor_sync(0xffffffffu, v, 1);
            v += __shfl_xor_sync(0xffffffffu, v, 2);
            if (t == 0) atomicAdd(&s_sum[wm * 32 + mi * 16 + g + hh * 8], v);
        }
    __syncthreads();
    if (tid < 128) atomicAdd(&g_sumexp[m0 + tid], s_sum[tid]);
}

__global__ __launch_bounds__(256) void recon_kernel(const float* __restrict__ base_rates,
                                                    const float* __restrict__ bows) {
    SOFTMAX_TILE_PROLOGUE

    float ps[2][2] = {{0.f, 0.f}, {0.f, 0.f}};
    float cS[2][2], lS[2][2];
#pragma unroll
    for (int mi = 0; mi < 2; mi++)
#pragma unroll
        for (int hh = 0; hh < 2; hh++) {
            float s = g_sumexp[m0 + wm * 32 + mi * 16 + g + hh * 8];
            cS[mi][hh] = 1e-6f * s;
            lS[mi][hh] = __logf(s);
        }
#pragma unroll
    for (int mi = 0; mi < 2; mi++)
#pragma unroll
        for (int ni = 0; ni < 8; ni++) {
            int v = v0 + wn * 64 + ni * 8 + 2 * t;
            if (v < VDIM) {
                float br0 = base_rates[v], br1 = base_rates[v + 1];
                int r1 = m0 + wm * 32 + mi * 16 + g;
                float2 bw1 = *reinterpret_cast<const float2*>(bows + (size_t)r1 * VDIM + v);
                float2 bw2 = *reinterpret_cast<const float2*>(bows + (size_t)(r1 + 8) * VDIM + v);
                ps[mi][0] += (__logf(__expf(acc[mi][ni][0] + br0) + cS[mi][0]) - lS[mi][0]) * bw1.x
                           + (__logf(__expf(acc[mi][ni][1] + br1) + cS[mi][0]) - lS[mi][0]) * bw1.y;
                ps[mi][1] += (__logf(__expf(acc[mi][ni][2] + br0) + cS[mi][1]) - lS[mi][1]) * bw2.x
                           + (__logf(__expf(acc[mi][ni][3] + br1) + cS[mi][1]) - lS[mi][1]) * bw2.y;
            }
        }
#pragma unroll
    for (int mi = 0; mi < 2; mi++)
#pragma unroll
        for (int hh = 0; hh < 2; hh++) {
            float v = ps[mi][hh];
            v += __shfl_xor_sync(0xffffffffu, v, 1);
            v += __shfl_xor_sync(0xffffffffu, v, 2);
            if (t == 0) atomicAdd(&s_sum[wm * 32 + mi * 16 + g + hh * 8], v);
        }
    __syncthreads();
    if (tid < 128) atomicAdd(&g_reconrow[m0 + tid], s_sum[tid]);
}

// ---------------- final deterministic reduction ----------------
__device__ float block_sum256(float x, float* red) {
    int tid = threadIdx.x;
    red[tid] = x;
    __syncthreads();
    for (int off = 128; off; off >>= 1) {
        if (tid < off) red[tid] += red[tid + off];
        __syncthreads();
    }
    float r = red[0];
    __syncthreads();
    return r;
}

__global__ void final_kernel(const float* __restrict__ labels, const float* __restrict__ base_rates,
                             const float* __restrict__ bow_w, const float* __restrict__ topic_w,
                             const float* __restrict__ bow_b, const float* __restrict__ topic_b,
                             float* __restrict__ out, int n_gamma_parts) {
    __shared__ float red[256];
    int tid = threadIdx.x;
    float sumRecon = 0.f, sumKld = 0.f, sumMse = 0.f, sumBase = 0.f, sumBw2 = 0.f, sumGam = 0.f;
    for (int b = tid; b < BDIM; b += 256) {
        sumRecon += g_reconrow[b];
        sumKld += g_kldrow[b];
        float pred = bow_b[0] + topic_b[0] + g_P[b * 64 + 50];
        for (int k = 0; k < KDIM; k++) {
            float th = g_theta[b * KDIM + k];
            pred += th * (g_P[b * 64 + k] + topic_w[k]);
        }
        float d = pred - labels[b];
        sumMse += d * d;
    }
    for (int v = tid; v < VDIM; v += 256) {
        sumBase += fabsf(base_rates[v]);
        float w = bow_w[v];
        sumBw2 += w * w;
    }
    for (int i = tid; i < n_gamma_parts; i += 256) sumGam += g_gammapart[i];

    float sr = block_sum256(sumRecon, red);
    float sk = block_sum256(sumKld, red);
    float sm = block_sum256(sumMse, red);
    float sb = block_sum256(sumBase, red);
    float sw2 = block_sum256(sumBw2, red);
    float sg = block_sum256(sumGam, red);
    if (tid == 0) {
        out[0] = -sr / (float)BDIM;
        out[1] = 0.0005f * sb + sm / (float)BDIM + 0.000005f * sg + 0.0005f * sqrtf(sw2);
        out[2] = -0.5f * sk / (float)BDIM;
    }
}

// ---------------- launch ----------------
extern "C" void kernel_launch(void* const* d_in, const int* in_sizes, int n_in,
                              void* d_out, int out_size) {
    const float* bows    = (const float*)d_in[0];
    const float* nb      = (const float*)d_in[1];
    const float* labels  = (const float*)d_in[2];
    const float* W1      = (const float*)d_in[3];
    const float* b1      = (const float*)d_in[4];
    const float* W2      = (const float*)d_in[5];
    const float* b2      = (const float*)d_in[6];
    const float* bn1g    = (const float*)d_in[7];
    const float* bn1b    = (const float*)d_in[8];
    const float* bn1m    = (const float*)d_in[9];
    const float* bn1v    = (const float*)d_in[10];
    const float* bn2g    = (const float*)d_in[11];
    const float* bn2b    = (const float*)d_in[12];
    const float* bn2m    = (const float*)d_in[13];
    const float* bn2v    = (const float*)d_in[14];
    const float* muW     = (const float*)d_in[15];
    const float* mub     = (const float*)d_in[16];
    const float* lsW     = (const float*)d_in[17];
    const float* lsb     = (const float*)d_in[18];
    const float* beta    = (const float*)d_in[19];
    const float* gam     = (const float*)d_in[20];
    const float* base    = (const float*)d_in[21];
    const float* bow_w   = (const float*)d_in[22];
    const float* bow_b   = (const float*)d_in[23];
    const float* topic_w = (const float*)d_in[24];
    const float* topic_b = (const float*)d_in[25];
    float* out = (float*)d_out;

    const int nGammaBlocks = (VDIM + 63) / 64;  // 782
    const int nVBlocks = (VDIM + 127) / 128;    // 391

    // attribute set only (no allocation) — needed for 61.4KB dynamic smem
    cudaFuncSetAttribute(gemm_big_kernel,
                         cudaFuncAttributeMaxDynamicSharedMemorySize, GB_SMEM_BYTES);

    prep_kernel<<<nGammaBlocks, 256>>>(beta, gam, bow_w);
    gemm_big_kernel<<<dim3(BDIM / BM, (NTOT + BNT - 1) / BNT, 24), 256, GB_SMEM_BYTES>>>(nb, W1);
    stage2_mma_kernel<<<dim3(BDIM / S2BM, (HDIM + S2BNT - 1) / S2BNT), 256>>>(
        b1, bn1g, bn1b, bn1m, bn1v, W2, b2, bn2g, bn2b, bn2m, bn2v);
    stage3_mma_kernel<<<dim3(BDIM / S2BM, (2 * KDIM + S2BNT - 1) / S2BNT), 256>>>(muW, lsW);
    stage3_fin_kernel<<<BDIM, 64>>>(mub, lsb);
    softmax_sum_kernel<<<dim3(BDIM / 128, nVBlocks), 256>>>(base);
    recon_kernel<<<dim3(BDIM / 128, nVBlocks), 256>>>(base, bows);
    final_kernel<<<1, 256>>>(labels, base, bow_w, topic_w, bow_b, topic_b, out, nGammaBlocks);
}

// round 17
// speedup vs baseline: 1.2664x; 1.0046x over previous
#include <cuda_runtime.h>
#include <cuda_bf16.h>
#include <cstdint>

// ---------------- problem constants ----------------
#define VDIM 50000
#define VPAD 50048          // 782*64, padded for bf16 beta array
#define KDIM 50
#define HDIM 300
#define BDIM 512
#define NTOT 351            // 300 (W1 cols) + 51 (sbeta/bow_w cols)
#define BN_EPS 1e-5f
#define S2_KPAD 320         // padded K for stage2/stage3 MMA

// ---------------- scratch (device globals; no allocs allowed) ----------------
__device__ float         g_hpre[BDIM * HDIM];           // 512x300
__device__ float         g_P[BDIM * 64];                // cols 0..49 = nb@sbeta, col 50 = nb@bow_w
__device__ float         g_h2[BDIM * HDIM];
__device__ float         g_muls[BDIM * 128];            // cols 0..49 = mu (raw), 50..99 = logsigma (raw)
__device__ float         g_theta[BDIM * KDIM];
__device__ __nv_bfloat16 g_thetab16[BDIM * 64];         // zero-padded to K=64
__device__ float         g_kldrow[BDIM];
__device__ float         g_sumexp[BDIM];                // per-row sum of exp(logits)
__device__ float         g_reconrow[BDIM];              // per-row recon sum (atomic accum)
__device__ float         g_gammapart[800];
__device__ float         g_sbetaT[51 * VDIM];           // rows 0..49: (beta*gamma)^T, row 50: bow_w
__device__ __nv_bfloat16 g_betab16[(size_t)VPAD * 64];  // beta rows as bf16, zero-padded

// ---------------- mma helper ----------------
__device__ __forceinline__ void mma_bf16(float* d, const unsigned* a, const unsigned* b) {
    asm volatile(
        "mma.sync.aligned.m16n8k16.row.col.f32.bf16.bf16.f32 "
        "{%0,%1,%2,%3}, {%4,%5,%6,%7}, {%8,%9}, {%0,%1,%2,%3};\n"
        : "+f"(d[0]), "+f"(d[1]), "+f"(d[2]), "+f"(d[3])
        : "r"(a[0]), "r"(a[1]), "r"(a[2]), "r"(a[3]), "r"(b[0]), "r"(b[1]));
}

__device__ __forceinline__ void split_hl(float x, __nv_bfloat16& h, __nv_bfloat16& l) {
    h = __float2bfloat16(x);
    l = __float2bfloat16(x - __bfloat162float(h));
}

// ---------------- prep: zeroing, sbetaT, bf16 beta, Sum|gamma| partials ----
__global__ __launch_bounds__(256) void prep_kernel(const float* __restrict__ beta,
                                                   const float* __restrict__ gam,
                                                   const float* __restrict__ bow_w) {
    __shared__ float tile[64][51];
    __shared__ float rs[256];
    int v0 = blockIdx.x * 64;
    int tid = threadIdx.x;

    // grid-stride zeroing (782 blocks x 256 = 200192 threads)
    int gtid = blockIdx.x * 256 + tid;
    if (gtid < BDIM * HDIM) g_hpre[gtid] = 0.f;
    if (gtid < BDIM * 64)   g_P[gtid] = 0.f;
    if (gtid < BDIM) { g_sumexp[gtid] = 0.f; g_reconrow[gtid] = 0.f; }

    float asum = 0.f;
    for (int idx = tid; idx < 64 * KDIM; idx += 256) {
        int r = idx / KDIM, c = idx % KDIM;
        int v = v0 + r;
        float s = 0.f;
        if (v < VDIM) {
            float bb = beta[(size_t)v * KDIM + c];
            float gg = gam[(size_t)v * KDIM + c];
            s = bb * gg;
            asum += fabsf(gg);
        }
        tile[r][c] = s;
    }
    // bf16 beta copy, zero-padded to [VPAD][64]
    for (int idx = tid; idx < 64 * 64; idx += 256) {
        int r = idx >> 6, c = idx & 63;
        int v = v0 + r;
        float val = (c < KDIM && v < VDIM) ? beta[(size_t)v * KDIM + c] : 0.f;
        g_betab16[(size_t)(v0 + r) * 64 + c] = __float2bfloat16(val);
    }
    __syncthreads();
    for (int idx = tid; idx < KDIM * 64; idx += 256) {
        int k = idx >> 6, j = idx & 63;
        int v = v0 + j;
        if (v < VDIM) g_sbetaT[(size_t)k * VDIM + v] = tile[j][k];
    }
    for (int j = tid; j < 64; j += 256) {
        int v = v0 + j;
        if (v < VDIM) g_sbetaT[(size_t)50 * VDIM + v] = bow_w[v];
    }
    rs[tid] = asum;
    __syncthreads();
    for (int off = 128; off; off >>= 1) {
        if (tid < off) rs[tid] += rs[tid + off];
        __syncthreads();
    }
    if (tid == 0) g_gammapart[blockIdx.x] = rs[0];
}

// =====================================================================
// Fused big GEMM: [hpre | P] = nb @ [W1 | sbetaT]^T
// A single bf16, B hi/lo split (2 MMAs). split-K x24. BNT=128 two-half.
// NEW: 3-buffer ring, ONE barrier per K-stage, loads prefetch 2 stages.
// Dynamic smem 92.2KB: sA | sBh | sBl, each [3][128][40] bf16.
// =====================================================================
#define BM 128
#define BNT 128
#define BK 32
#define SPLIT_LEN 2112          // 66 * 32 ; 24 splits cover 50688 >= 50000
#define NSTAGES (SPLIT_LEN / BK)
#define GB_SEG (3 * 128 * 40)   // bf16 elements per operand buffer (3-ring)
#define GB_SMEM_BYTES (3 * GB_SEG * 2)

__global__ __launch_bounds__(256) void gemm_big_kernel(const float* __restrict__ A,
                                                       const float* __restrict__ W1) {
    extern __shared__ __nv_bfloat16 dsm[];
#define SA_(buf,r,k)  dsm[((buf) * 128 + (r)) * 40 + (k)]
#define SBH_(buf,r,k) dsm[GB_SEG + ((buf) * 128 + (r)) * 40 + (k)]
#define SBL_(buf,r,k) dsm[2 * GB_SEG + ((buf) * 128 + (r)) * 40 + (k)]

    const int tid = threadIdx.x;
    const int m0 = blockIdx.x * BM;
    const int n0 = blockIdx.y * BNT;
    const int kstart = blockIdx.z * SPLIT_LEN;

    const int warpId = tid >> 5, lane = tid & 31;
    const int wm = warpId >> 1, wn = warpId & 1;
    const int g = lane >> 2, t = lane & 3;

    float acc[2][2][4][4];
#pragma unroll
    for (int hf = 0; hf < 2; hf++)
#pragma unroll
        for (int mi = 0; mi < 2; mi++)
#pragma unroll
            for (int ni = 0; ni < 4; ni++)
#pragma unroll
                for (int e = 0; e < 4; e++) acc[hf][mi][ni][e] = 0.f;

    float4 ra[4], rb[4];

    auto ldA = [&](int stage) {
        int kb = kstart + stage * BK;
#pragma unroll
        for (int q = 0; q < 4; q++) {
            int qi = tid + q * 256;
            int r = qi >> 3;
            int k = kb + (qi & 7) * 4;
            float4 v = make_float4(0.f, 0.f, 0.f, 0.f);
            if (k < VDIM) v = *reinterpret_cast<const float4*>(A + (size_t)(m0 + r) * VDIM + k);
            ra[q] = v;
        }
    };
    auto ldB = [&](int stage) {
        int kb = kstart + stage * BK;
#pragma unroll
        for (int q = 0; q < 4; q++) {
            int qi = tid + q * 256;
            int r = qi >> 3;
            int k = kb + (qi & 7) * 4;
            int n = n0 + r;
            float4 v = make_float4(0.f, 0.f, 0.f, 0.f);
            if (k < VDIM && n < NTOT) {
                const float* src = (n < HDIM) ? (W1 + (size_t)n * VDIM)
                                              : (g_sbetaT + (size_t)(n - HDIM) * VDIM);
                v = *reinterpret_cast<const float4*>(src + k);
            }
            rb[q] = v;
        }
    };
    auto stAB = [&](int buf) {
#pragma unroll
        for (int q = 0; q < 4; q++) {
            int qi = tid + q * 256;
            int r = qi >> 3;
            int kq = (qi & 7) * 4;
            SA_(buf, r, kq)     = __float2bfloat16(ra[q].x);
            SA_(buf, r, kq + 1) = __float2bfloat16(ra[q].y);
            SA_(buf, r, kq + 2) = __float2bfloat16(ra[q].z);
            SA_(buf, r, kq + 3) = __float2bfloat16(ra[q].w);
        }
#pragma unroll
        for (int q = 0; q < 4; q++) {
            int qi = tid + q * 256;
            int r = qi >> 3;
            int kq = (qi & 7) * 4;
            const float* pv = &rb[q].x;
#pragma unroll
            for (int e = 0; e < 4; e++) {
                __nv_bfloat16 h, l;
                split_hl(pv[e], h, l);
                SBH_(buf, r, kq + e) = h;
                SBL_(buf, r, kq + e) = l;
            }
        }
    };
    auto compute = [&](int buf) {
#pragma unroll
        for (int kk = 0; kk < BK; kk += 16) {
            unsigned af[2][4];
#pragma unroll
            for (int mi = 0; mi < 2; mi++) {
                int r = wm * 32 + mi * 16 + g;
                af[mi][0] = *reinterpret_cast<const unsigned*>(&SA_(buf, r, kk + 2 * t));
                af[mi][1] = *reinterpret_cast<const unsigned*>(&SA_(buf, r + 8, kk + 2 * t));
                af[mi][2] = *reinterpret_cast<const unsigned*>(&SA_(buf, r, kk + 8 + 2 * t));
                af[mi][3] = *reinterpret_cast<const unsigned*>(&SA_(buf, r + 8, kk + 8 + 2 * t));
            }
#pragma unroll
            for (int hf = 0; hf < 2; hf++) {
                unsigned bh[4][2], bl[4][2];
#pragma unroll
                for (int ni = 0; ni < 4; ni++) {
                    int n = hf * 64 + wn * 32 + ni * 8 + g;
                    bh[ni][0] = *reinterpret_cast<const unsigned*>(&SBH_(buf, n, kk + 2 * t));
                    bh[ni][1] = *reinterpret_cast<const unsigned*>(&SBH_(buf, n, kk + 8 + 2 * t));
                    bl[ni][0] = *reinterpret_cast<const unsigned*>(&SBL_(buf, n, kk + 2 * t));
                    bl[ni][1] = *reinterpret_cast<const unsigned*>(&SBL_(buf, n, kk + 8 + 2 * t));
                }
#pragma unroll
                for (int mi = 0; mi < 2; mi++)
#pragma unroll
                    for (int ni = 0; ni < 4; ni++) {
                        mma_bf16(acc[hf][mi][ni], af[mi], bh[ni]);
                        mma_bf16(acc[hf][mi][ni], af[mi], bl[ni]);
                    }
            }
        }
    };

    // 3-buffer ring: iter s stores stage s+1, loads stage s+2, ONE barrier, computes s.
    ldA(0); ldB(0);
    stAB(0);
    ldA(1); ldB(1);
    for (int s = 0; s < NSTAGES; s++) {
        if (s + 1 < NSTAGES) stAB((s + 1) % 3);
        if (s + 2 < NSTAGES) { ldA(s + 2); ldB(s + 2); }
        __syncthreads();
        compute(s % 3);
    }

#pragma unroll
    for (int hf = 0; hf < 2; hf++)
#pragma unroll
        for (int mi = 0; mi < 2; mi++)
#pragma unroll
            for (int ni = 0; ni < 4; ni++)
#pragma unroll
                for (int e = 0; e < 4; e++) {
                    int row = m0 + wm * 32 + mi * 16 + g + ((e >= 2) ? 8 : 0);
                    int col = n0 + hf * 64 + wn * 32 + ni * 8 + 2 * t + (e & 1);
                    float v = acc[hf][mi][ni][e];
                    if (col < HDIM) atomicAdd(&g_hpre[row * HDIM + col], v);
                    else if (col < NTOT) atomicAdd(&g_P[row * 64 + (col - HDIM)], v);
                }
#undef SA_
#undef SBH_
#undef SBL_
}

// =====================================================================
// stage2 (bn1 fused): h2 = bn2(relu( bn1(relu(hpre+b1)) @ W2^T + b2 ))
// =====================================================================
#define S2BM 64
#define S2BNT 32
#define S2_NSTAGES (S2_KPAD / BK)   // 10

__global__ __launch_bounds__(256) void stage2_mma_kernel(
    const float* __restrict__ b1_, const float* __restrict__ bn1g,
    const float* __restrict__ bn1b, const float* __restrict__ bn1m,
    const float* __restrict__ bn1v,
    const float* __restrict__ W2, const float* __restrict__ b2,
    const float* __restrict__ bn2g, const float* __restrict__ bn2b,
    const float* __restrict__ bn2m, const float* __restrict__ bn2v) {
    __shared__ __nv_bfloat16 sA[2][S2BM][BK + 8];
    __shared__ __nv_bfloat16 sBh[2][S2BNT][BK + 8];
    __shared__ __nv_bfloat16 sBl[2][S2BNT][BK + 8];
    __shared__ float sb1[S2_KPAD], sA1[S2_KPAD], sA0[S2_KPAD];

    const int tid = threadIdx.x;
    const int m0 = blockIdx.x * S2BM;
    const int n0 = blockIdx.y * S2BNT;

    const int warpId = tid >> 5, lane = tid & 31;
    const int wm2 = warpId >> 2, wn2 = warpId & 3;
    const int g = lane >> 2, t = lane & 3;

    for (int c = tid; c < S2_KPAD; c += 256) {
        float s = 0.f, a0 = 0.f, bb = 0.f;
        if (c < HDIM) {
            s = rsqrtf(bn1v[c] + BN_EPS) * bn1g[c];
            a0 = bn1b[c] - bn1m[c] * s;
            bb = b1_[c];
        }
        sb1[c] = bb; sA1[c] = s; sA0[c] = a0;
    }
    __syncthreads();

    float acc[2][4];
#pragma unroll
    for (int mi = 0; mi < 2; mi++)
#pragma unroll
        for (int e = 0; e < 4; e++) acc[mi][e] = 0.f;

    float4 ra[2], rb;

    auto ldA = [&](int stage) {
        int kb = stage * BK;
#pragma unroll
        for (int q = 0; q < 2; q++) {
            int qi = tid + q * 256;
            int r = qi >> 3;
            int kq = (qi & 7) * 4;
            int k = kb + kq;
            float4 v = make_float4(0.f, 0.f, 0.f, 0.f);
            if (k < HDIM) v = *reinterpret_cast<const float4*>(g_hpre + (m0 + r) * HDIM + k);
            float* pv = &v.x;
#pragma unroll
            for (int e = 0; e < 4; e++) {
                float val = fmaxf(pv[e] + sb1[k + e], 0.f);
                pv[e] = val * sA1[k + e] + sA0[k + e];
            }
            ra[q] = v;
        }
    };
    auto ldB = [&](int stage) {
        int kb = stage * BK;
        int r = tid >> 3;
        int kq = (tid & 7) * 4;
        int k = kb + kq;
        int n = n0 + r;
        float4 v = make_float4(0.f, 0.f, 0.f, 0.f);
        if (k < HDIM && n < HDIM) v = *reinterpret_cast<const float4*>(W2 + (size_t)n * HDIM + k);
        rb = v;
    };
    auto stAB = [&](int buf) {
#pragma unroll
        for (int q = 0; q < 2; q++) {
            int qi = tid + q * 256;
            int r = qi >> 3;
            int kq = (qi & 7) * 4;
            sA[buf][r][kq]     = __float2bfloat16(ra[q].x);
            sA[buf][r][kq + 1] = __float2bfloat16(ra[q].y);
            sA[buf][r][kq + 2] = __float2bfloat16(ra[q].z);
            sA[buf][r][kq + 3] = __float2bfloat16(ra[q].w);
        }
        {
            int r = tid >> 3;
            int kq = (tid & 7) * 4;
            const float* pv = &rb.x;
#pragma unroll
            for (int e = 0; e < 4; e++) {
                __nv_bfloat16 h, l;
                split_hl(pv[e], h, l);
                sBh[buf][r][kq + e] = h;
                sBl[buf][r][kq + e] = l;
            }
        }
    };
    auto compute = [&](int buf) {
#pragma unroll
        for (int kk = 0; kk < BK; kk += 16) {
            unsigned af[2][4], bh[2], bl[2];
#pragma unroll
            for (int mi = 0; mi < 2; mi++) {
                int r = wm2 * 32 + mi * 16 + g;
                af[mi][0] = *reinterpret_cast<const unsigned*>(&sA[buf][r][kk + 2 * t]);
                af[mi][1] = *reinterpret_cast<const unsigned*>(&sA[buf][r + 8][kk + 2 * t]);
                af[mi][2] = *reinterpret_cast<const unsigned*>(&sA[buf][r][kk + 8 + 2 * t]);
                af[mi][3] = *reinterpret_cast<const unsigned*>(&sA[buf][r + 8][kk + 8 + 2 * t]);
            }
            {
                int n = wn2 * 8 + g;
                bh[0] = *reinterpret_cast<const unsigned*>(&sBh[buf][n][kk + 2 * t]);
                bh[1] = *reinterpret_cast<const unsigned*>(&sBh[buf][n][kk + 8 + 2 * t]);
                bl[0] = *reinterpret_cast<const unsigned*>(&sBl[buf][n][kk + 2 * t]);
                bl[1] = *reinterpret_cast<const unsigned*>(&sBl[buf][n][kk + 8 + 2 * t]);
            }
#pragma unroll
            for (int mi = 0; mi < 2; mi++) {
                mma_bf16(acc[mi], af[mi], bh);
                mma_bf16(acc[mi], af[mi], bl);
            }
        }
    };

    ldA(0); ldB(0);
    stAB(0);
    __syncthreads();
    for (int s = 0; s < S2_NSTAGES; s++) {
        int cur = s & 1;
        if (s + 1 < S2_NSTAGES) { ldA(s + 1); ldB(s + 1); }
        compute(cur);
        if (s + 1 < S2_NSTAGES) {
            __syncthreads();
            stAB(cur ^ 1);
            __syncthreads();
        }
    }

#pragma unroll
    for (int mi = 0; mi < 2; mi++)
#pragma unroll
        for (int e = 0; e < 4; e++) {
            int row = m0 + wm2 * 32 + mi * 16 + g + ((e >= 2) ? 8 : 0);
            int col = n0 + wn2 * 8 + 2 * t + (e & 1);
            if (col < HDIM) {
                float x = fmaxf(acc[mi][e] + b2[col], 0.f);
                x = (x - bn2m[col]) * rsqrtf(bn2v[col] + BN_EPS) * bn2g[col] + bn2b[col];
                g_h2[row * HDIM + col] = x;
            }
        }
}

// =====================================================================
// stage3 MMA: [mu | ls](raw) = h2 @ [muW ; lsW]^T   (N=100)
// =====================================================================
__global__ __launch_bounds__(256) void stage3_mma_kernel(const float* __restrict__ muW,
                                                         const float* __restrict__ lsW) {
    __shared__ __nv_bfloat16 sA[2][S2BM][BK + 8];
    __shared__ __nv_bfloat16 sBh[2][S2BNT][BK + 8];
    __shared__ __nv_bfloat16 sBl[2][S2BNT][BK + 8];

    const int tid = threadIdx.x;
    const int m0 = blockIdx.x * S2BM;
    const int n0 = blockIdx.y * S2BNT;

    const int warpId = tid >> 5, lane = tid & 31;
    const int wm2 = warpId >> 2, wn2 = warpId & 3;
    const int g = lane >> 2, t = lane & 3;

    float acc[2][4];
#pragma unroll
    for (int mi = 0; mi < 2; mi++)
#pragma unroll
        for (int e = 0; e < 4; e++) acc[mi][e] = 0.f;

    float4 ra[2], rb;

    auto ldA = [&](int stage) {
        int kb = stage * BK;
#pragma unroll
        for (int q = 0; q < 2; q++) {
            int qi = tid + q * 256;
            int r = qi >> 3;
            int kq = (qi & 7) * 4;
            int k = kb + kq;
            float4 v = make_float4(0.f, 0.f, 0.f, 0.f);
            if (k < HDIM) v = *reinterpret_cast<const float4*>(g_h2 + (m0 + r) * HDIM + k);
            ra[q] = v;
        }
    };
    auto ldB = [&](int stage) {
        int kb = stage * BK;
        int r = tid >> 3;
        int kq = (tid & 7) * 4;
        int k = kb + kq;
        int n = n0 + r;
        float4 v = make_float4(0.f, 0.f, 0.f, 0.f);
        if (k < HDIM && n < 2 * KDIM) {
            const float* src = (n < KDIM) ? (muW + (size_t)n * HDIM)
                                          : (lsW + (size_t)(n - KDIM) * HDIM);
            v = *reinterpret_cast<const float4*>(src + k);
        }
        rb = v;
    };
    auto stAB = [&](int buf) {
#pragma unroll
        for (int q = 0; q < 2; q++) {
            int qi = tid + q * 256;
            int r = qi >> 3;
            int kq = (qi & 7) * 4;
            sA[buf][r][kq]     = __float2bfloat16(ra[q].x);
            sA[buf][r][kq + 1] = __float2bfloat16(ra[q].y);
            sA[buf][r][kq + 2] = __float2bfloat16(ra[q].z);
            sA[buf][r][kq + 3] = __float2bfloat16(ra[q].w);
        }
        {
            int r = tid >> 3;
            int kq = (tid & 7) * 4;
            const float* pv = &rb.x;
#pragma unroll
            for (int e = 0; e < 4; e++) {
                __nv_bfloat16 h, l;
                split_hl(pv[e], h, l);
                sBh[buf][r][kq + e] = h;
                sBl[buf][r][kq + e] = l;
            }
        }
    };
    auto compute = [&](int buf) {
#pragma unroll
        for (int kk = 0; kk < BK; kk += 16) {
            unsigned af[2][4], bh[2], bl[2];
#pragma unroll
            for (int mi = 0; mi < 2; mi++) {
                int r = wm2 * 32 + mi * 16 + g;
                af[mi][0] = *reinterpret_cast<const unsigned*>(&sA[buf][r][kk + 2 * t]);
                af[mi][1] = *reinterpret_cast<const unsigned*>(&sA[buf][r + 8][kk + 2 * t]);
                af[mi][2] = *reinterpret_cast<const unsigned*>(&sA[buf][r][kk + 8 + 2 * t]);
                af[mi][3] = *reinterpret_cast<const unsigned*>(&sA[buf][r + 8][kk + 8 + 2 * t]);
            }
            {
                int n = wn2 * 8 + g;
                bh[0] = *reinterpret_cast<const unsigned*>(&sBh[buf][n][kk + 2 * t]);
                bh[1] = *reinterpret_cast<const unsigned*>(&sBh[buf][n][kk + 8 + 2 * t]);
                bl[0] = *reinterpret_cast<const unsigned*>(&sBl[buf][n][kk + 2 * t]);
                bl[1] = *reinterpret_cast<const unsigned*>(&sBl[buf][n][kk + 8 + 2 * t]);
            }
#pragma unroll
            for (int mi = 0; mi < 2; mi++) {
                mma_bf16(acc[mi], af[mi], bh);
                mma_bf16(acc[mi], af[mi], bl);
            }
        }
    };

    ldA(0); ldB(0);
    stAB(0);
    __syncthreads();
    for (int s = 0; s < S2_NSTAGES; s++) {
        int cur = s & 1;
        if (s + 1 < S2_NSTAGES) { ldA(s + 1); ldB(s + 1); }
        compute(cur);
        if (s + 1 < S2_NSTAGES) {
            __syncthreads();
            stAB(cur ^ 1);
            __syncthreads();
        }
    }

#pragma unroll
    for (int mi = 0; mi < 2; mi++)
#pragma unroll
        for (int e = 0; e < 4; e++) {
            int row = m0 + wm2 * 32 + mi * 16 + g + ((e >= 2) ? 8 : 0);
            int col = n0 + wn2 * 8 + 2 * t + (e & 1);
            if (col < 2 * KDIM) g_muls[row * 128 + col] = acc[mi][e];
        }
}

// ---------------- stage3 finish: bias + softmax + theta + kld ----------------
__global__ void stage3_fin_kernel(const float* __restrict__ mub, const float* __restrict__ lsb) {
    int b = blockIdx.x;
    int tid = threadIdx.x;   // 64 threads
    __shared__ float mus[KDIM];
    __shared__ float klds[64];
    __shared__ float red2[2];
    float kld_part = 0.f;
    if (tid < KDIM) {
        float mu = g_muls[b * 128 + tid] + mub[tid];
        float ls = g_muls[b * 128 + KDIM + tid] + lsb[tid];
        mus[tid] = mu;
        kld_part = 1.f + ls - mu * mu - __expf(ls);
    }
    klds[tid] = (tid < KDIM) ? kld_part : 0.f;
    __syncthreads();
    if (tid == 0) {
        float mx = -1e30f;
        for (int k = 0; k < KDIM; k++) mx = fmaxf(mx, mus[k]);
        float s = 0.f;
        for (int k = 0; k < KDIM; k++) s += __expf(mus[k] - mx);
        red2[0] = mx; red2[1] = s;
        float kk = 0.f;
        for (int k = 0; k < KDIM; k++) kk += klds[k];
        g_kldrow[b] = kk;
    }
    __syncthreads();
    if (tid < KDIM) {
        float th = __expf(mus[tid] - red2[0]) / red2[1];
        g_theta[b * KDIM + tid] = th;
        g_thetab16[b * 64 + tid] = __float2bfloat16(th);
    } else {
        g_thetab16[b * 64 + tid] = __float2bfloat16(0.f);
    }
}

// =====================================================================
// Softmax passes: recompute logits tiles; sB from precomputed bf16 beta.
// =====================================================================
#define SOFTMAX_TILE_PROLOGUE                                                              \
    __shared__ __nv_bfloat16 sA[128][72];                                                  \
    __shared__ __nv_bfloat16 sB[128][72];                                                  \
    __shared__ float s_sum[128];                                                           \
    int tid = threadIdx.x;                                                                 \
    int m0 = blockIdx.x * 128, v0 = blockIdx.y * 128;                                      \
    for (int i = tid; i < 128; i += 256) s_sum[i] = 0.f;                                   \
    _Pragma("unroll")                                                                      \
    for (int q = 0; q < 4; q++) {                                                          \
        int qi = tid + q * 256;                                                            \
        int r = qi >> 3;                                                                   \
        int c8 = (qi & 7) * 8;                                                             \
        uint4 u = *reinterpret_cast<const uint4*>(&g_thetab16[(m0 + r) * 64 + c8]);        \
        *reinterpret_cast<uint4*>(&sA[r][c8]) = u;                                         \
        uint4 ub = *reinterpret_cast<const uint4*>(&g_betab16[(size_t)(v0 + r) * 64 + c8]);\
        *reinterpret_cast<uint4*>(&sB[r][c8]) = ub;                                        \
    }                                                                                      \
    __syncthreads();                                                                       \
    const int warpId = tid >> 5, lane = tid & 31;                                          \
    const int wm = warpId >> 1, wn = warpId & 1;                                           \
    const int g = lane >> 2, t = lane & 3;                                                 \
    float acc[2][8][4];                                                                    \
    _Pragma("unroll")                                                                      \
    for (int mi = 0; mi < 2; mi++)                                                         \
        _Pragma("unroll")                                                                  \
        for (int ni = 0; ni < 8; ni++)                                                     \
            _Pragma("unroll")                                                              \
            for (int e = 0; e < 4; e++) acc[mi][ni][e] = 0.f;                              \
    _Pragma("unroll")                                                                      \
    for (int kk = 0; kk < 64; kk += 16) {                                                  \
        unsigned af[2][4], bfr[8][2];                                                      \
        _Pragma("unroll")                                                                  \
        for (int mi = 0; mi < 2; mi++) {                                                   \
            int r = wm * 32 + mi * 16 + g;                                                 \
            af[mi][0] = *reinterpret_cast<const unsigned*>(&sA[r][kk + 2 * t]);            \
            af[mi][1] = *reinterpret_cast<const unsigned*>(&sA[r + 8][kk + 2 * t]);        \
            af[mi][2] = *reinterpret_cast<const unsigned*>(&sA[r][kk + 8 + 2 * t]);        \
            af[mi][3] = *reinterpret_cast<const unsigned*>(&sA[r + 8][kk + 8 + 2 * t]);    \
        }                                                                                  \
        _Pragma("unroll")                                                                  \
        for (int ni = 0; ni < 8; ni++) {                                                   \
            int n = wn * 64 + ni * 8 + g;                                                  \
            bfr[ni][0] = *reinterpret_cast<const unsigned*>(&sB[n][kk + 2 * t]);           \
            bfr[ni][1] = *reinterpret_cast<const unsigned*>(&sB[n][kk + 8 + 2 * t]);       \
        }                                                                                  \
        _Pragma("unroll")                                                                  \
        for (int mi = 0; mi < 2; mi++)                                                     \
            _Pragma("unroll")                                                              \
            for (int ni = 0; ni < 8; ni++) mma_bf16(acc[mi][ni], af[mi], bfr[ni]);         \
    }

__global__ __launch_bounds__(256) void softmax_sum_kernel(const float* __restrict__ base_rates) {
    SOFTMAX_TILE_PROLOGUE

    float ps[2][2] = {{0.f, 0.f}, {0.f, 0.f}};
#pragma unroll
    for (int mi = 0; mi < 2; mi++)
#pragma unroll
        for (int ni = 0; ni < 8; ni++) {
            int v = v0 + wn * 64 + ni * 8 + 2 * t;
            if (v < VDIM) {
                float br0 = base_rates[v], br1 = base_rates[v + 1];
                ps[mi][0] += __expf(acc[mi][ni][0] + br0) + __expf(acc[mi][ni][1] + br1);
                ps[mi][1] += __expf(acc[mi][ni][2] + br0) + __expf(acc[mi][ni][3] + br1);
            }
        }
#pragma unroll
    for (int mi = 0; mi < 2; mi++)
#pragma unroll
        for (int hh = 0; hh < 2; hh++) {
            float v = ps[mi][hh];
            v += __shfl_xor_sync(0xffffffffu, v, 1);
            v += __shfl_xor_sync(0xffffffffu, v, 2);
            if (t == 0) atomicAdd(&s_sum[wm * 32 + mi * 16 + g + hh * 8], v);
        }
    __syncthreads();
    if (tid < 128) atomicAdd(&g_sumexp[m0 + tid], s_sum[tid]);
}

__global__ __launch_bounds__(256) void recon_kernel(const float* __restrict__ base_rates,
                                                    const float* __restrict__ bows) {
    SOFTMAX_TILE_PROLOGUE

    float ps[2][2] = {{0.f, 0.f}, {0.f, 0.f}};
    float cS[2][2], lS[2][2];
#pragma unroll
    for (int mi = 0; mi < 2; mi++)
#pragma unroll
        for (int hh = 0; hh < 2; hh++) {
            float s = g_sumexp[m0 + wm * 32 + mi * 16 + g + hh * 8];
            cS[mi][hh] = 1e-6f * s;
            lS[mi][hh] = __logf(s);
        }
#pragma unroll
    for (int mi = 0; mi < 2; mi++)
#pragma unroll
        for (int ni = 0; ni < 8; ni++) {
            int v = v0 + wn * 64 + ni * 8 + 2 * t;
            if (v < VDIM) {
                float br0 = base_rates[v], br1 = base_rates[v + 1];
                int r1 = m0 + wm * 32 + mi * 16 + g;
                float2 bw1 = *reinterpret_cast<const float2*>(bows + (size_t)r1 * VDIM + v);
                float2 bw2 = *reinterpret_cast<const float2*>(bows + (size_t)(r1 + 8) * VDIM + v);
                ps[mi][0] += (__logf(__expf(acc[mi][ni][0] + br0) + cS[mi][0]) - lS[mi][0]) * bw1.x
                           + (__logf(__expf(acc[mi][ni][1] + br1) + cS[mi][0]) - lS[mi][0]) * bw1.y;
                ps[mi][1] += (__logf(__expf(acc[mi][ni][2] + br0) + cS[mi][1]) - lS[mi][1]) * bw2.x
                           + (__logf(__expf(acc[mi][ni][3] + br1) + cS[mi][1]) - lS[mi][1]) * bw2.y;
            }
        }
#pragma unroll
    for (int mi = 0; mi < 2; mi++)
#pragma unroll
        for (int hh = 0; hh < 2; hh++) {
            float v = ps[mi][hh];
            v += __shfl_xor_sync(0xffffffffu, v, 1);
            v += __shfl_xor_sync(0xffffffffu, v, 2);
            if (t == 0) atomicAdd(&s_sum[wm * 32 + mi * 16 + g + hh * 8], v);
        }
    __syncthreads();
    if (tid < 128) atomicAdd(&g_reconrow[m0 + tid], s_sum[tid]);
}

// ---------------- final deterministic reduction ----------------
__device__ float block_sum256(float x, float* red) {
    int tid = threadIdx.x;
    red[tid] = x;
    __syncthreads();
    for (int off = 128; off; off >>= 1) {
        if (tid < off) red[tid] += red[tid + off];
        __syncthreads();
    }
    float r = red[0];
    __syncthreads();
    return r;
}

__global__ void final_kernel(const float* __restrict__ labels, const float* __restrict__ base_rates,
                             const float* __restrict__ bow_w, const float* __restrict__ topic_w,
                             const float* __restrict__ bow_b, const float* __restrict__ topic_b,
                             float* __restrict__ out, int n_gamma_parts) {
    __shared__ float red[256];
    int tid = threadIdx.x;
    float sumRecon = 0.f, sumKld = 0.f, sumMse = 0.f, sumBase = 0.f, sumBw2 = 0.f, sumGam = 0.f;
    for (int b = tid; b < BDIM; b += 256) {
        sumRecon += g_reconrow[b];
        sumKld += g_kldrow[b];
        float pred = bow_b[0] + topic_b[0] + g_P[b * 64 + 50];
        for (int k = 0; k < KDIM; k++) {
            float th = g_theta[b * KDIM + k];
            pred += th * (g_P[b * 64 + k] + topic_w[k]);
        }
        float d = pred - labels[b];
        sumMse += d * d;
    }
    for (int v = tid; v < VDIM; v += 256) {
        sumBase += fabsf(base_rates[v]);
        float w = bow_w[v];
        sumBw2 += w * w;
    }
    for (int i = tid; i < n_gamma_parts; i += 256) sumGam += g_gammapart[i];

    float sr = block_sum256(sumRecon, red);
    float sk = block_sum256(sumKld, red);
    float sm = block_sum256(sumMse, red);
    float sb = block_sum256(sumBase, red);
    float sw2 = block_sum256(sumBw2, red);
    float sg = block_sum256(sumGam, red);
    if (tid == 0) {
        out[0] = -sr / (float)BDIM;
        out[1] = 0.0005f * sb + sm / (float)BDIM + 0.000005f * sg + 0.0005f * sqrtf(sw2);
        out[2] = -0.5f * sk / (float)BDIM;
    }
}

// ---------------- launch ----------------
extern "C" void kernel_launch(void* const* d_in, const int* in_sizes, int n_in,
                              void* d_out, int out_size) {
    const float* bows    = (const float*)d_in[0];
    const float* nb      = (const float*)d_in[1];
    const float* labels  = (const float*)d_in[2];
    const float* W1      = (const float*)d_in[3];
    const float* b1      = (const float*)d_in[4];
    const float* W2      = (const float*)d_in[5];
    const float* b2      = (const float*)d_in[6];
    const float* bn1g    = (const float*)d_in[7];
    const float* bn1b    = (const float*)d_in[8];
    const float* bn1m    = (const float*)d_in[9];
    const float* bn1v    = (const float*)d_in[10];
    const float* bn2g    = (const float*)d_in[11];
    const float* bn2b    = (const float*)d_in[12];
    const float* bn2m    = (const float*)d_in[13];
    const float* bn2v    = (const float*)d_in[14];
    const float* muW     = (const float*)d_in[15];
    const float* mub     = (const float*)d_in[16];
    const float* lsW     = (const float*)d_in[17];
    const float* lsb     = (const float*)d_in[18];
    const float* beta    = (const float*)d_in[19];
    const float* gam     = (const float*)d_in[20];
    const float* base    = (const float*)d_in[21];
    const float* bow_w   = (const float*)d_in[22];
    const float* bow_b   = (const float*)d_in[23];
    const float* topic_w = (const float*)d_in[24];
    const float* topic_b = (const float*)d_in[25];
    float* out = (float*)d_out;

    const int nGammaBlocks = (VDIM + 63) / 64;  // 782
    const int nVBlocks = (VDIM + 127) / 128;    // 391

    // attribute set only (no allocation) — needed for 92.2KB dynamic smem
    cudaFuncSetAttribute(gemm_big_kernel,
                         cudaFuncAttributeMaxDynamicSharedMemorySize, GB_SMEM_BYTES);

    prep_kernel<<<nGammaBlocks, 256>>>(beta, gam, bow_w);
    gemm_big_kernel<<<dim3(BDIM / BM, (NTOT + BNT - 1) / BNT, 24), 256, GB_SMEM_BYTES>>>(nb, W1);
    stage2_mma_kernel<<<dim3(BDIM / S2BM, (HDIM + S2BNT - 1) / S2BNT), 256>>>(
        b1, bn1g, bn1b, bn1m, bn1v, W2, b2, bn2g, bn2b, bn2m, bn2v);
    stage3_mma_kernel<<<dim3(BDIM / S2BM, (2 * KDIM + S2BNT - 1) / S2BNT), 256>>>(muW, lsW);
    stage3_fin_kernel<<<BDIM, 64>>>(mub, lsb);
    softmax_sum_kernel<<<dim3(BDIM / 128, nVBlocks), 256>>>(base);
    recon_kernel<<<dim3(BDIM / 128, nVBlocks), 256>>>(base, bows);
    final_kernel<<<1, 256>>>(labels, base, bow_w, topic_w, bow_b, topic_b, out, nGammaBlocks);
}